// round 5
// baseline (speedup 1.0000x reference)
#include <cuda_runtime.h>
#include <cuda_bf16.h>
#include <math.h>
#include <stdint.h>

// ----------------------------------------------------------------------------
// RelNet forward on tcgen05 (sm_103a), bf16 hi/lo split GEMMs, 2-stage pipeline
// N=64, C=64, H=W=8 (HW=64), E=256, G=512, GIN=388
// ----------------------------------------------------------------------------

#if defined(__CUDA_ARCH__) && (defined(__CUDA_ARCH_FEAT_SM103_ALL) || \
    defined(__CUDA_ARCH_FEAT_SM100_ALL) || defined(__CUDA_ARCH_FEAT_SM101_ALL))
#define TC_OK 1
#else
#define TC_OK 0
#endif

#define NB   64
#define HW   64
#define FDIM 66
#define G    512
#define E    256
#define MROWS (NB * HW * HW)   // 262144

#define BM 128
#define BN 256
#define BK 64
#define KTILES (G / BK)        // 8
#define THREADS 256

// SMEM: [tmemptr][mbar0][mbar1][bias 1KB] then 2 stages of (Ahi16K|Alo16K|Bhi32K|Blo32K)
#define S_OFF_TMEM 0
#define S_OFF_MB0  8
#define S_OFF_MB1  16
#define S_OFF_BIAS 32
#define STAGE_SZ   98304
#define ST_A_HI(b) (2048 + (b) * STAGE_SZ)
#define ST_A_LO(b) (ST_A_HI(b) + 16384)
#define ST_B_HI(b) (ST_A_LO(b) + 16384)
#define ST_B_LO(b) (ST_B_HI(b) + 32768)
#define SMEM_SZ    (2048 + 2 * STAGE_SZ)   // 198656

// idesc: kind::f16, dtype=F32, atype=BF16, btype=BF16, N=256, M=128
#define MMA_IDESC ((1u<<4)|(1u<<7)|(1u<<10)|(32u<<17)|(8u<<24))

#define SMEM_DESC_BASE_SW128 \
    ((uint64_t(2)<<61)|(uint64_t(1)<<46)|(uint64_t(64)<<32)|(uint64_t(1)<<16))
#define MAKE_SMEM_DESC(a) (SMEM_DESC_BASE_SW128 | ((uint64_t)((a) >> 4) & 0x3FFF))
#define SWZ(o) ((o) ^ (((o) >> 3) & 0x70))

// ---------------- device scratch (separate hi/lo planes) ----------------
__device__ unsigned short g_h2h[(size_t)MROWS * G], g_h2l[(size_t)MROWS * G];
__device__ unsigned short g_h3h[(size_t)MROWS * G], g_h3l[(size_t)MROWS * G];
__device__ float          g_Ai[(size_t)NB * HW * G];
__device__ float          g_Bj[(size_t)NB * HW * G];
__device__ float          g_Cq[NB * G];
__device__ float          g_part[(size_t)(MROWS / BM) * G];  // 2048 x 512
__device__ float          g_ctx[NB * G];
__device__ unsigned short g_w2h[G * G], g_w2l[G * G];
__device__ unsigned short g_w3h[G * G], g_w3l[G * G];
__device__ unsigned short g_w4h[G * G], g_w4l[G * G];

// ---------------- generic helpers ----------------
__device__ __forceinline__ void split2(float v0, float v1, unsigned &hi, unsigned &lo) {
    __nv_bfloat16 h0 = __float2bfloat16_rn(v0), h1 = __float2bfloat16_rn(v1);
    float l0f = v0 - __bfloat162float(h0), l1f = v1 - __bfloat162float(h1);
    __nv_bfloat16 l0 = __float2bfloat16_rn(l0f), l1 = __float2bfloat16_rn(l1f);
    hi = (unsigned)__bfloat16_as_ushort(h0) | ((unsigned)__bfloat16_as_ushort(h1) << 16);
    lo = (unsigned)__bfloat16_as_ushort(l0) | ((unsigned)__bfloat16_as_ushort(l1) << 16);
}
__device__ __forceinline__ float us2f(unsigned short u) {
    return __bfloat162float(__ushort_as_bfloat16(u));
}

#if TC_OK
// ---------------- tcgen05 / async PTX helpers (sm_103a only) ----------------
__device__ __forceinline__ uint32_t smem_u32(const void* p) {
    uint32_t a;
    asm("{ .reg .u64 t; cvta.to.shared.u64 t, %1; cvt.u32.u64 %0, t; }"
        : "=r"(a) : "l"(p));
    return a;
}
__device__ __forceinline__ uint32_t elect_one() {
    uint32_t p;
    asm volatile("{ .reg .pred p; elect.sync _|p, 0xFFFFFFFF; selp.b32 %0,1,0,p; }"
                 : "=r"(p));
    return p;
}
__device__ __forceinline__ void mma_bf16_ss(uint32_t d, uint64_t ad, uint64_t bd,
                                            uint32_t idesc, uint32_t en) {
    asm volatile(
        "{\n\t.reg .pred p;\n\tsetp.ne.u32 p, %4, 0;\n\t"
        "tcgen05.mma.cta_group::1.kind::f16 [%0], %1, %2, %3, {%5,%5,%5,%5}, p;\n\t}"
        :: "r"(d), "l"(ad), "l"(bd), "r"(idesc), "r"(en), "r"(0u) : "memory");
}
#define TC_ALLOC(sp, n)  asm volatile("tcgen05.alloc.cta_group::1.sync.aligned.shared::cta.b32 [%0], %1;" :: "r"(sp), "r"(n) : "memory")
#define TC_RELINQ()      asm volatile("tcgen05.relinquish_alloc_permit.cta_group::1.sync.aligned;")
#define TC_DEALLOC(t, n) asm volatile("tcgen05.dealloc.cta_group::1.sync.aligned.b32 %0, %1;" :: "r"(t), "r"(n))
#define TC_COMMIT(mb)    asm volatile("tcgen05.commit.cta_group::1.mbarrier::arrive::one.shared::cluster.b64 [%0];" :: "r"(mb) : "memory")
#define TC_FENCE_AFTER() asm volatile("tcgen05.fence::after_thread_sync;" ::: "memory")
#define TC_WAIT_LD()     asm volatile("tcgen05.wait::ld.sync.aligned;" ::: "memory")
#define FENCE_ASYNC()    asm volatile("fence.proxy.async.shared::cta;" ::: "memory")
#define MBAR_INIT(mb, c) asm volatile("mbarrier.init.shared.b64 [%0], %1;" :: "r"(mb), "r"(c) : "memory")
#define MBAR_INVAL(mb)   asm volatile("mbarrier.inval.shared.b64 [%0];" :: "r"(mb) : "memory")
#define CP16(dst, src)   asm volatile("cp.async.cg.shared.global [%0], [%1], 16;" :: "r"(dst), "l"(src) : "memory")
#define CP_COMMIT()      asm volatile("cp.async.commit_group;" ::: "memory")
#define CP_WAIT(n)       asm volatile("cp.async.wait_group %0;" :: "n"(n) : "memory")

__device__ __forceinline__ void mbar_wait(uint32_t mb, uint32_t parity) {
    asm volatile(
        "{\n\t.reg .pred P;\n\t"
        "WL_%=:\n\t"
        "mbarrier.try_wait.parity.acquire.cta.shared::cta.b64 P, [%0], %1, 0x989680;\n\t"
        "@P bra.uni WD_%=;\n\t"
        "bra.uni WL_%=;\n\t"
        "WD_%=:\n\t}"
        :: "r"(mb), "r"(parity) : "memory");
}
#define TC_LD_X32(r, a) \
    asm volatile("tcgen05.ld.sync.aligned.32x32b.x32.b32 " \
        "{%0,%1,%2,%3,%4,%5,%6,%7,%8,%9,%10,%11,%12,%13,%14,%15," \
        "%16,%17,%18,%19,%20,%21,%22,%23,%24,%25,%26,%27,%28,%29,%30,%31}, [%32];" \
        : "=r"((r)[0]),"=r"((r)[1]),"=r"((r)[2]),"=r"((r)[3]), \
          "=r"((r)[4]),"=r"((r)[5]),"=r"((r)[6]),"=r"((r)[7]), \
          "=r"((r)[8]),"=r"((r)[9]),"=r"((r)[10]),"=r"((r)[11]), \
          "=r"((r)[12]),"=r"((r)[13]),"=r"((r)[14]),"=r"((r)[15]), \
          "=r"((r)[16]),"=r"((r)[17]),"=r"((r)[18]),"=r"((r)[19]), \
          "=r"((r)[20]),"=r"((r)[21]),"=r"((r)[22]),"=r"((r)[23]), \
          "=r"((r)[24]),"=r"((r)[25]),"=r"((r)[26]),"=r"((r)[27]), \
          "=r"((r)[28]),"=r"((r)[29]),"=r"((r)[30]),"=r"((r)[31]) \
        : "r"(a))
#endif  // TC_OK

// ---- K1: Ai = feat_i @ W1a, Bj = feat_j @ W1b ------------------------------
__global__ void k_ab(const float* __restrict__ img, const float* __restrict__ w1) {
    int row = blockIdx.x;           // 0..4095
    int n = row >> 6, p = row & 63;
    __shared__ float f[FDIM];
    int tid = threadIdx.x;          // 512
    if (tid < 64) f[tid] = img[((size_t)n * 64 + tid) * 64 + p];
    else if (tid == 64) f[64] = (float)(p >> 3);
    else if (tid == 65) f[65] = (float)(p & 7);
    __syncthreads();
    float a0 = 0.f, a1 = 0.f, b0 = 0.f, b1 = 0.f;
    #pragma unroll 8
    for (int c = 0; c < 64; c += 2) {
        a0 = fmaf(f[c],     w1[(size_t)c * G + tid], a0);
        a1 = fmaf(f[c + 1], w1[(size_t)(c + 1) * G + tid], a1);
        b0 = fmaf(f[c],     w1[(size_t)(c + FDIM) * G + tid], b0);
        b1 = fmaf(f[c + 1], w1[(size_t)(c + 1 + FDIM) * G + tid], b1);
    }
    a0 = fmaf(f[64], w1[(size_t)64 * G + tid], a0);
    a1 = fmaf(f[65], w1[(size_t)65 * G + tid], a1);
    b0 = fmaf(f[64], w1[(size_t)(64 + FDIM) * G + tid], b0);
    b1 = fmaf(f[65], w1[(size_t)(65 + FDIM) * G + tid], b1);
    g_Ai[(size_t)row * G + tid] = a0 + a1;
    g_Bj[(size_t)row * G + tid] = b0 + b1;
}

// ---- K2: Cq = ques @ W1c + b1 ----------------------------------------------
__global__ void k_cq(const float* __restrict__ ques, const float* __restrict__ w1,
                     const float* __restrict__ b1) {
    int n = blockIdx.x, tid = threadIdx.x;    // 512 threads
    __shared__ float q[E];
    if (tid < E) q[tid] = ques[n * E + tid];
    __syncthreads();
    float s0 = b1[tid], s1 = 0.f;
    #pragma unroll 8
    for (int e = 0; e < E; e += 2) {
        s0 = fmaf(q[e],     w1[(size_t)(2 * FDIM + e) * G + tid], s0);
        s1 = fmaf(q[e + 1], w1[(size_t)(2 * FDIM + e + 1) * G + tid], s1);
    }
    g_Cq[n * G + tid] = s0 + s1;
}

// ---- weight prep: transpose + bf16 hi/lo split for all 3 weights -----------
__global__ void k_wprep3(const float* __restrict__ W2, const float* __restrict__ W3,
                         const float* __restrict__ W4,
                         unsigned short* __restrict__ h2, unsigned short* __restrict__ l2,
                         unsigned short* __restrict__ h3, unsigned short* __restrict__ l3,
                         unsigned short* __restrict__ h4, unsigned short* __restrict__ l4) {
    int k = blockIdx.x, n = threadIdx.x;      // 512 x 512, y selects matrix
    const float* W = (blockIdx.y == 0) ? W2 : (blockIdx.y == 1) ? W3 : W4;
    unsigned short* hi = (blockIdx.y == 0) ? h2 : (blockIdx.y == 1) ? h3 : h4;
    unsigned short* lo = (blockIdx.y == 0) ? l2 : (blockIdx.y == 1) ? l3 : l4;
    float v = W[(size_t)k * G + n];
    __nv_bfloat16 h = __float2bfloat16_rn(v);
    float hf = __bfloat162float(h);
    __nv_bfloat16 l = __float2bfloat16_rn(v - hf);
    hi[(size_t)n * G + k] = __bfloat16_as_ushort(h);
    lo[(size_t)n * G + k] = __bfloat16_as_ushort(l);
}

// ---- main tcgen05 GEMM (double-buffered) -----------------------------------
// MODE 0: A built from relu(Ai+Bj+Cq); MODE 1: A from planes; MODE 2: + fused mean
template<int MODE>
__global__ __launch_bounds__(THREADS, 1)
void k_mma(const unsigned short* __restrict__ aHi, const unsigned short* __restrict__ aLo,
           const unsigned short* __restrict__ wHi, const unsigned short* __restrict__ wLo,
           const float* __restrict__ bias,
           unsigned short* __restrict__ oHi, unsigned short* __restrict__ oLo) {
    extern __shared__ char smem[];
#if TC_OK
    const uint32_t sbase = smem_u32(smem);
    const int tid  = threadIdx.x;
    const int wid  = tid >> 5;
    const int lane = tid & 31;
    const int mBlk = blockIdx.x;              // 0..2047
    const int nBase = blockIdx.y * BN;        // 0 or 256

    const uint32_t S_TMEM = sbase + S_OFF_TMEM;
    float* sBias = (float*)(smem + S_OFF_BIAS);

    if (wid == 0) { TC_ALLOC(S_TMEM, 256); TC_RELINQ(); }
    if (tid == 0) { MBAR_INIT(sbase + S_OFF_MB0, 1); MBAR_INIT(sbase + S_OFF_MB1, 1); }
    sBias[tid] = bias[nBase + tid];
    __syncthreads();
    uint32_t tmem;
    asm volatile("ld.shared.b32 %0, [%1];" : "=r"(tmem) : "r"(S_TMEM));

    // stage loader
    auto load_stage = [&](int kt, int b) {
        const int kB = kt * BK;
        if (MODE == 0) {
            #pragma unroll
            for (int it = 0; it < 8; ++it) {
                int idx = tid + it * 256;             // 2048 = 128 rows x 16 f4
                int r = idx >> 4, c4 = idx & 15;
                size_t gr = (size_t)mBlk * BM + r;
                int n = (int)(gr >> 12), i = ((int)gr >> 6) & 63, j = (int)gr & 63;
                const float4 a4 = *(const float4*)&g_Ai[((size_t)(n * 64 + i)) * G + kB + c4 * 4];
                const float4 b4 = *(const float4*)&g_Bj[((size_t)(n * 64 + j)) * G + kB + c4 * 4];
                const float4 q4 = *(const float4*)&g_Cq[(size_t)n * G + kB + c4 * 4];
                float v0 = fmaxf(a4.x + b4.x + q4.x, 0.f);
                float v1 = fmaxf(a4.y + b4.y + q4.y, 0.f);
                float v2 = fmaxf(a4.z + b4.z + q4.z, 0.f);
                float v3 = fmaxf(a4.w + b4.w + q4.w, 0.f);
                unsigned h01, l01, h23, l23;
                split2(v0, v1, h01, l01);
                split2(v2, v3, h23, l23);
                unsigned off = SWZ((unsigned)(r * 128 + c4 * 8));
                *(uint2*)(smem + ST_A_HI(b) + off) = make_uint2(h01, h23);
                *(uint2*)(smem + ST_A_LO(b) + off) = make_uint2(l01, l23);
            }
        } else {
            #pragma unroll
            for (int it = 0; it < 4; ++it) {
                int idx = tid + it * 256;             // 1024 = 128 rows x 8 chunks
                int r = idx >> 3, c = idx & 7;
                size_t gsrc = ((size_t)mBlk * BM + r) * G + kB + c * 8;
                unsigned off = SWZ((unsigned)(r * 128 + c * 16));
                CP16(sbase + ST_A_HI(b) + off, &aHi[gsrc]);
                CP16(sbase + ST_A_LO(b) + off, &aLo[gsrc]);
            }
        }
        #pragma unroll
        for (int it = 0; it < 8; ++it) {
            int idx = tid + it * 256;                 // 2048 = 256 rows x 8 chunks
            int r = idx >> 3, c = idx & 7;
            size_t gsrc = (size_t)(nBase + r) * G + kB + c * 8;
            unsigned off = SWZ((unsigned)(r * 128 + c * 16));
            CP16(sbase + ST_B_HI(b) + off, &wHi[gsrc]);
            CP16(sbase + ST_B_LO(b) + off, &wLo[gsrc]);
        }
        CP_COMMIT();
    };

    load_stage(0, 0);

    for (int t = 0; t < KTILES; ++t) {
        const int b = t & 1;
        if (t + 1 < KTILES) {
            if (t >= 1) mbar_wait(sbase + (((t + 1) & 1) ? S_OFF_MB1 : S_OFF_MB0),
                                  ((t - 1) >> 1) & 1);
            load_stage(t + 1, (t + 1) & 1);
            CP_WAIT(1);
        } else {
            CP_WAIT(0);
        }
        __syncthreads();
        if (wid == 0 && elect_one()) {
            FENCE_ASYNC();
            uint64_t adH = MAKE_SMEM_DESC(sbase + ST_A_HI(b));
            uint64_t adL = MAKE_SMEM_DESC(sbase + ST_A_LO(b));
            uint64_t bdH = MAKE_SMEM_DESC(sbase + ST_B_HI(b));
            uint64_t bdL = MAKE_SMEM_DESC(sbase + ST_B_LO(b));
            #pragma unroll
            for (int s = 0; s < 4; ++s) {
                uint64_t o = (uint64_t)(s * 2);
                mma_bf16_ss(tmem, adH + o, bdH + o, MMA_IDESC, (t | s) ? 1u : 0u);
                mma_bf16_ss(tmem, adH + o, bdL + o, MMA_IDESC, 1u);
                mma_bf16_ss(tmem, adL + o, bdH + o, MMA_IDESC, 1u);
            }
            TC_COMMIT(sbase + (b ? S_OFF_MB1 : S_OFF_MB0));
        }
    }

    // last commit on mbar1: commit index 3 -> parity 1
    mbar_wait(sbase + S_OFF_MB1, 1);
    TC_FENCE_AFTER();

    // ---- epilogue ----
    float* sPart = (float*)(smem + ST_A_HI(0));   // [4][256] for MODE 2
    if (wid < 4) {
        int lrow = wid * 32 + lane;
        size_t grow = (size_t)mBlk * BM + lrow;
        #pragma unroll 1
        for (int cp2 = 0; cp2 < 4; ++cp2) {
            uint32_t rA[32], rB[32];
            TC_LD_X32(rA, tmem + (cp2 * 2) * 32);
            TC_LD_X32(rB, tmem + (cp2 * 2 + 1) * 32);
            TC_WAIT_LD();
            #pragma unroll
            for (int h = 0; h < 2; ++h) {
                uint32_t* r = h ? rB : rA;
                int cc = (cp2 * 2 + h) * 32;
                if (MODE < 2) {
                    #pragma unroll
                    for (int q = 0; q < 4; ++q) {
                        unsigned hw[4], lw[4];
                        #pragma unroll
                        for (int e = 0; e < 4; ++e) {
                            float v0 = fmaxf(__uint_as_float(r[q*8+e*2])   + sBias[cc+q*8+e*2],   0.f);
                            float v1 = fmaxf(__uint_as_float(r[q*8+e*2+1]) + sBias[cc+q*8+e*2+1], 0.f);
                            split2(v0, v1, hw[e], lw[e]);
                        }
                        size_t go = grow * G + nBase + cc + q * 8;
                        *(uint4*)&oHi[go] = make_uint4(hw[0], hw[1], hw[2], hw[3]);
                        *(uint4*)&oLo[go] = make_uint4(lw[0], lw[1], lw[2], lw[3]);
                    }
                } else {
                    #pragma unroll
                    for (int j = 0; j < 32; ++j) {
                        float v = fmaxf(__uint_as_float(r[j]) + sBias[cc + j], 0.f);
                        #pragma unroll
                        for (int o = 16; o > 0; o >>= 1)
                            v += __shfl_xor_sync(0xFFFFFFFFu, v, o);
                        if (lane == 0) sPart[wid * 256 + cc + j] = v;
                    }
                }
            }
        }
    }
    __syncthreads();
    if (MODE == 2) {
        float s = sPart[tid] + sPart[256 + tid] + sPart[512 + tid] + sPart[768 + tid];
        g_part[(size_t)mBlk * G + nBase + tid] = s;
        __syncthreads();
    }
    if (tid == 0) { MBAR_INVAL(sbase + S_OFF_MB0); MBAR_INVAL(sbase + S_OFF_MB1); }
    __syncthreads();
    if (wid == 0) TC_DEALLOC(tmem, 256);
#else
    // -------- scalar fallback (non-sm_103a compile passes only) --------
    const int tid  = threadIdx.x;
    const int mBlk = blockIdx.x;
    const int nBase = blockIdx.y * BN;
    const int col = nBase + tid;
    float colsum = 0.f;
    for (int r = 0; r < BM; ++r) {
        size_t gr = (size_t)mBlk * BM + r;
        float acc = bias[col];
        int n = (int)(gr >> 12), i = ((int)gr >> 6) & 63, j = (int)gr & 63;
        for (int k = 0; k < G; ++k) {
            float a;
            if (MODE == 0) {
                float raw = fmaxf(g_Ai[((size_t)(n * 64 + i)) * G + k]
                                + g_Bj[((size_t)(n * 64 + j)) * G + k]
                                + g_Cq[(size_t)n * G + k], 0.f);
                unsigned hh, ll;
                split2(raw, 0.f, hh, ll);
                a = us2f((unsigned short)(hh & 0xFFFFu)) + us2f((unsigned short)(ll & 0xFFFFu));
            } else {
                a = us2f(aHi[gr * G + k]) + us2f(aLo[gr * G + k]);
            }
            float w = us2f(wHi[(size_t)col * G + k]) + us2f(wLo[(size_t)col * G + k]);
            acc = fmaf(a, w, acc);
        }
        float v = fmaxf(acc, 0.f);
        if (MODE < 2) {
            unsigned hh, ll;
            split2(v, 0.f, hh, ll);
            oHi[gr * G + col] = (unsigned short)(hh & 0xFFFFu);
            oLo[gr * G + col] = (unsigned short)(ll & 0xFFFFu);
        } else colsum += v;
    }
    if (MODE == 2) g_part[(size_t)mBlk * G + col] = colsum;
#endif
}

// ---- final mean over 4096 pairs (32 partial blocks per image) --------------
__global__ void k_reduce2() {
    int n = blockIdx.x, k = threadIdx.x;   // 64 x 512
    float s = 0.f;
    #pragma unroll
    for (int b = 0; b < 32; ++b)
        s += g_part[(size_t)(n * 32 + b) * G + k];
    g_ctx[n * G + k] = s * (1.0f / 4096.0f);
}

// ---- f-MLP + log_softmax ---------------------------------------------------
__global__ void k_fmlp(const float* __restrict__ fw1, const float* __restrict__ fb1,
                       const float* __restrict__ fw2, const float* __restrict__ fb2,
                       const float* __restrict__ fw3, const float* __restrict__ fb3,
                       float* __restrict__ out) {
    int n = blockIdx.x, tid = threadIdx.x;   // 512 threads
    __shared__ float x[G], y[G];
    __shared__ float sc[2];
    x[tid] = g_ctx[n * G + tid];
    __syncthreads();
    float s0 = fb1[tid], s1 = 0.f;
    #pragma unroll 8
    for (int c = 0; c < G; c += 2) {
        s0 = fmaf(x[c],     fw1[(size_t)c * G + tid], s0);
        s1 = fmaf(x[c + 1], fw1[(size_t)(c + 1) * G + tid], s1);
    }
    y[tid] = fmaxf(s0 + s1, 0.f);
    __syncthreads();
    s0 = fb2[tid]; s1 = 0.f;
    #pragma unroll 8
    for (int c = 0; c < G; c += 2) {
        s0 = fmaf(y[c],     fw2[(size_t)c * G + tid], s0);
        s1 = fmaf(y[c + 1], fw2[(size_t)(c + 1) * G + tid], s1);
    }
    x[tid] = fmaxf(s0 + s1, 0.f);
    __syncthreads();
    if (tid < 2) {
        float t = fb3[tid];
        for (int c = 0; c < G; ++c) t = fmaf(x[c], fw3[c * 2 + tid], t);
        sc[tid] = t;
    }
    __syncthreads();
    if (tid == 0) {
        float m = fmaxf(sc[0], sc[1]);
        float lse = m + logf(expf(sc[0] - m) + expf(sc[1] - m));
        out[n * 2 + 0] = sc[0] - lse;
        out[n * 2 + 1] = sc[1] - lse;
    }
}

// ----------------------------------------------------------------------------
extern "C" void kernel_launch(void* const* d_in, const int* in_sizes, int n_in,
                              void* d_out, int out_size) {
    const float* img  = (const float*)d_in[0];
    const float* ques = (const float*)d_in[1];
    const float* g_w1 = (const float*)d_in[2];
    const float* g_b1 = (const float*)d_in[3];
    const float* g_w2 = (const float*)d_in[4];
    const float* g_b2 = (const float*)d_in[5];
    const float* g_w3 = (const float*)d_in[6];
    const float* g_b3 = (const float*)d_in[7];
    const float* g_w4 = (const float*)d_in[8];
    const float* g_b4 = (const float*)d_in[9];
    const float* f_w1 = (const float*)d_in[10];
    const float* f_b1 = (const float*)d_in[11];
    const float* f_w2 = (const float*)d_in[12];
    const float* f_b2 = (const float*)d_in[13];
    const float* f_w3 = (const float*)d_in[14];
    const float* f_b3 = (const float*)d_in[15];
    float* out = (float*)d_out;

    cudaFuncSetAttribute(k_mma<0>, cudaFuncAttributeMaxDynamicSharedMemorySize, SMEM_SZ);
    cudaFuncSetAttribute(k_mma<1>, cudaFuncAttributeMaxDynamicSharedMemorySize, SMEM_SZ);
    cudaFuncSetAttribute(k_mma<2>, cudaFuncAttributeMaxDynamicSharedMemorySize, SMEM_SZ);

    unsigned short *w2h, *w2l, *w3h, *w3l, *w4h, *w4l, *h2h, *h2l, *h3h, *h3l;
    cudaGetSymbolAddress((void**)&w2h, g_w2h); cudaGetSymbolAddress((void**)&w2l, g_w2l);
    cudaGetSymbolAddress((void**)&w3h, g_w3h); cudaGetSymbolAddress((void**)&w3l, g_w3l);
    cudaGetSymbolAddress((void**)&w4h, g_w4h); cudaGetSymbolAddress((void**)&w4l, g_w4l);
    cudaGetSymbolAddress((void**)&h2h, g_h2h); cudaGetSymbolAddress((void**)&h2l, g_h2l);
    cudaGetSymbolAddress((void**)&h3h, g_h3h); cudaGetSymbolAddress((void**)&h3l, g_h3l);

    k_wprep3<<<dim3(G, 3), G>>>(g_w2, g_w3, g_w4, w2h, w2l, w3h, w3l, w4h, w4l);
    k_ab<<<NB * HW, 512>>>(img, g_w1);
    k_cq<<<NB, 512>>>(ques, g_w1, g_b1);

    dim3 gg(MROWS / BM, G / BN);   // 2048 x 2
    k_mma<0><<<gg, THREADS, SMEM_SZ>>>(nullptr, nullptr, w2h, w2l, g_b2, h2h, h2l);
    k_mma<1><<<gg, THREADS, SMEM_SZ>>>(h2h, h2l, w3h, w3l, g_b3, h3h, h3l);
    k_mma<2><<<gg, THREADS, SMEM_SZ>>>(h3h, h3l, w4h, w4l, g_b4, nullptr, nullptr);

    k_reduce2<<<NB, 512>>>();
    k_fmlp<<<NB, 512>>>(f_w1, f_b1, f_w2, f_b2, f_w3, f_b3, out);
}

// round 7
// speedup vs baseline: 1.2742x; 1.2742x over previous
#include <cuda_runtime.h>
#include <cuda_bf16.h>
#include <math.h>
#include <stdint.h>

// ----------------------------------------------------------------------------
// RelNet forward, tcgen05 sm_103a, bf16 hi/lo split, warp-specialized pipeline
// N=64, C=64, H=W=8 (HW=64), E=256, G=512, GIN=388
// ----------------------------------------------------------------------------

#if defined(__CUDA_ARCH__) && (defined(__CUDA_ARCH_FEAT_SM103_ALL) || \
    defined(__CUDA_ARCH_FEAT_SM100_ALL) || defined(__CUDA_ARCH_FEAT_SM101_ALL))
#define TC_OK 1
#else
#define TC_OK 0
#endif

#define NB   64
#define HW   64
#define FDIM 66
#define G    512
#define E    256
#define MROWS (NB * HW * HW)   // 262144

#define BM 128
#define BN 256
#define BK 32
#define TITER (G / BK)         // 16 pipeline iterations
#define THREADS 256

// SMEM control block + 2 stages of (Ahi8K|Alo8K|Bhi16K|Blo16K) = 48KB each
#define S_TMEM_O  0
#define S_FULL(b) (8 + (b) * 8)      // 8, 16
#define S_FREE(b) (24 + (b) * 8)     // 24, 32
#define S_DONE    40
#define S_BIAS    64                 // 256 floats
#define STAGE_SZ  49152
#define ST_A_HI(b) (2048 + (b) * STAGE_SZ)
#define ST_A_LO(b) (ST_A_HI(b) + 8192)
#define ST_B_HI(b) (ST_A_HI(b) + 16384)
#define ST_B_LO(b) (ST_A_HI(b) + 32768)
#define SMEM_SZ    (2048 + 2 * STAGE_SZ)   // 100352 -> 2 CTAs/SM

// idesc: kind::f16, dtype=F32, atype=BF16, btype=BF16, N=256, M=128
#define MMA_IDESC ((1u<<4)|(1u<<7)|(1u<<10)|(32u<<17)|(8u<<24))

// SW64 K-major descriptor (layout=4, version=1, SBO=32, LBO=1); 64B rows
#define SMEM_DESC_BASE_SW64 \
    ((uint64_t(4)<<61)|(uint64_t(1)<<46)|(uint64_t(32)<<32)|(uint64_t(1)<<16))
#define MAKE_DESC64(a) (SMEM_DESC_BASE_SW64 | ((uint64_t)((a) >> 4) & 0x3FFF))
#define SWZ64(o) ((o) ^ (((o) >> 3) & 0x30))

// ---------------- device scratch (separate hi/lo planes) ----------------
__device__ unsigned short g_h2h[(size_t)MROWS * G], g_h2l[(size_t)MROWS * G];
__device__ unsigned short g_h3h[(size_t)MROWS * G], g_h3l[(size_t)MROWS * G];
__device__ float          g_Ai[(size_t)NB * HW * G];
__device__ float          g_Bj[(size_t)NB * HW * G];
__device__ float          g_Cq[NB * G];
__device__ float          g_part[(size_t)(MROWS / BM) * G];  // 2048 x 512
__device__ float          g_ctx[NB * G];
__device__ unsigned short g_w2h[G * G], g_w2l[G * G];
__device__ unsigned short g_w3h[G * G], g_w3l[G * G];
__device__ unsigned short g_w4h[G * G], g_w4l[G * G];

// ---------------- generic helpers ----------------
__device__ __forceinline__ void split2(float v0, float v1, unsigned &hi, unsigned &lo) {
    __nv_bfloat16 h0 = __float2bfloat16_rn(v0), h1 = __float2bfloat16_rn(v1);
    float l0f = v0 - __bfloat162float(h0), l1f = v1 - __bfloat162float(h1);
    __nv_bfloat16 l0 = __float2bfloat16_rn(l0f), l1 = __float2bfloat16_rn(l1f);
    hi = (unsigned)__bfloat16_as_ushort(h0) | ((unsigned)__bfloat16_as_ushort(h1) << 16);
    lo = (unsigned)__bfloat16_as_ushort(l0) | ((unsigned)__bfloat16_as_ushort(l1) << 16);
}
__device__ __forceinline__ float us2f(unsigned short u) {
    return __bfloat162float(__ushort_as_bfloat16(u));
}

#if TC_OK
// ---------------- tcgen05 / async PTX helpers (sm_103a only) ----------------
__device__ __forceinline__ uint32_t smem_u32(const void* p) {
    uint32_t a;
    asm("{ .reg .u64 t; cvta.to.shared.u64 t, %1; cvt.u32.u64 %0, t; }"
        : "=r"(a) : "l"(p));
    return a;
}
__device__ __forceinline__ uint32_t elect_one() {
    uint32_t p;
    asm volatile("{ .reg .pred p; elect.sync _|p, 0xFFFFFFFF; selp.b32 %0,1,0,p; }"
                 : "=r"(p));
    return p;
}
__device__ __forceinline__ void mma_bf16_ss(uint32_t d, uint64_t ad, uint64_t bd,
                                            uint32_t idesc, uint32_t en) {
    asm volatile(
        "{\n\t.reg .pred p;\n\tsetp.ne.u32 p, %4, 0;\n\t"
        "tcgen05.mma.cta_group::1.kind::f16 [%0], %1, %2, %3, {%5,%5,%5,%5}, p;\n\t}"
        :: "r"(d), "l"(ad), "l"(bd), "r"(idesc), "r"(en), "r"(0u) : "memory");
}
#define TC_ALLOC(sp, n)  asm volatile("tcgen05.alloc.cta_group::1.sync.aligned.shared::cta.b32 [%0], %1;" :: "r"(sp), "r"(n) : "memory")
#define TC_RELINQ()      asm volatile("tcgen05.relinquish_alloc_permit.cta_group::1.sync.aligned;")
#define TC_DEALLOC(t, n) asm volatile("tcgen05.dealloc.cta_group::1.sync.aligned.b32 %0, %1;" :: "r"(t), "r"(n))
#define TC_COMMIT(mb)    asm volatile("tcgen05.commit.cta_group::1.mbarrier::arrive::one.shared::cluster.b64 [%0];" :: "r"(mb) : "memory")
#define TC_FENCE_AFTER() asm volatile("tcgen05.fence::after_thread_sync;" ::: "memory")
#define TC_WAIT_LD()     asm volatile("tcgen05.wait::ld.sync.aligned;" ::: "memory")
#define FENCE_ASYNC()    asm volatile("fence.proxy.async.shared::cta;" ::: "memory")
#define MBAR_INIT(mb, c) asm volatile("mbarrier.init.shared.b64 [%0], %1;" :: "r"(mb), "r"(c) : "memory")
#define MBAR_INVAL(mb)   asm volatile("mbarrier.inval.shared.b64 [%0];" :: "r"(mb) : "memory")
#define MBAR_ARRIVE(mb)  asm volatile("mbarrier.arrive.release.cta.shared::cta.b64 _, [%0];" :: "r"(mb) : "memory")
#define CP16(dst, src)   asm volatile("cp.async.cg.shared.global [%0], [%1], 16;" :: "r"(dst), "l"(src) : "memory")
#define CP_COMMIT()      asm volatile("cp.async.commit_group;" ::: "memory")
#define CP_WAIT0()       asm volatile("cp.async.wait_group 0;" ::: "memory")

__device__ __forceinline__ void mbar_wait(uint32_t mb, uint32_t parity) {
    asm volatile(
        "{\n\t.reg .pred P;\n\t"
        "WL_%=:\n\t"
        "mbarrier.try_wait.parity.acquire.cta.shared::cta.b64 P, [%0], %1, 0x989680;\n\t"
        "@P bra.uni WD_%=;\n\t"
        "bra.uni WL_%=;\n\t"
        "WD_%=:\n\t}"
        :: "r"(mb), "r"(parity) : "memory");
}
#define TC_LD_X32(r, a) \
    asm volatile("tcgen05.ld.sync.aligned.32x32b.x32.b32 " \
        "{%0,%1,%2,%3,%4,%5,%6,%7,%8,%9,%10,%11,%12,%13,%14,%15," \
        "%16,%17,%18,%19,%20,%21,%22,%23,%24,%25,%26,%27,%28,%29,%30,%31}, [%32];" \
        : "=r"((r)[0]),"=r"((r)[1]),"=r"((r)[2]),"=r"((r)[3]), \
          "=r"((r)[4]),"=r"((r)[5]),"=r"((r)[6]),"=r"((r)[7]), \
          "=r"((r)[8]),"=r"((r)[9]),"=r"((r)[10]),"=r"((r)[11]), \
          "=r"((r)[12]),"=r"((r)[13]),"=r"((r)[14]),"=r"((r)[15]), \
          "=r"((r)[16]),"=r"((r)[17]),"=r"((r)[18]),"=r"((r)[19]), \
          "=r"((r)[20]),"=r"((r)[21]),"=r"((r)[22]),"=r"((r)[23]), \
          "=r"((r)[24]),"=r"((r)[25]),"=r"((r)[26]),"=r"((r)[27]), \
          "=r"((r)[28]),"=r"((r)[29]),"=r"((r)[30]),"=r"((r)[31]) \
        : "r"(a))
#endif  // TC_OK

// ---- K1: Ai = feat_i @ W1a, Bj = feat_j @ W1b (8 positions per block) ------
__global__ void k_ab(const float* __restrict__ img, const float* __restrict__ w1) {
    int n = blockIdx.x, pg = blockIdx.y;     // 64 x 8
    int tid = threadIdx.x;                   // 512
    __shared__ float f[8][FDIM];
    if (tid < 64) {
        int c = tid;
        #pragma unroll
        for (int p8 = 0; p8 < 8; ++p8)
            f[p8][c] = img[((size_t)n * 64 + c) * 64 + pg * 8 + p8];
    } else if (tid < 72) {
        int p8 = tid - 64, p = pg * 8 + p8;
        f[p8][64] = (float)(p >> 3);
        f[p8][65] = (float)(p & 7);
    }
    __syncthreads();
    float a[8] = {0,0,0,0,0,0,0,0}, b[8] = {0,0,0,0,0,0,0,0};
    #pragma unroll 2
    for (int c = 0; c < FDIM; ++c) {
        float wa = w1[(size_t)c * G + tid];
        float wb = w1[(size_t)(c + FDIM) * G + tid];
        #pragma unroll
        for (int p8 = 0; p8 < 8; ++p8) {
            a[p8] = fmaf(f[p8][c], wa, a[p8]);
            b[p8] = fmaf(f[p8][c], wb, b[p8]);
        }
    }
    #pragma unroll
    for (int p8 = 0; p8 < 8; ++p8) {
        int row = n * 64 + pg * 8 + p8;
        g_Ai[(size_t)row * G + tid] = a[p8];
        g_Bj[(size_t)row * G + tid] = b[p8];
    }
}

// ---- K2: Cq = ques @ W1c + b1 ----------------------------------------------
__global__ void k_cq(const float* __restrict__ ques, const float* __restrict__ w1,
                     const float* __restrict__ b1) {
    int n = blockIdx.x, tid = threadIdx.x;    // 512 threads
    __shared__ float q[E];
    if (tid < E) q[tid] = ques[n * E + tid];
    __syncthreads();
    float s0 = b1[tid], s1 = 0.f;
    #pragma unroll 8
    for (int e = 0; e < E; e += 2) {
        s0 = fmaf(q[e],     w1[(size_t)(2 * FDIM + e) * G + tid], s0);
        s1 = fmaf(q[e + 1], w1[(size_t)(2 * FDIM + e + 1) * G + tid], s1);
    }
    g_Cq[n * G + tid] = s0 + s1;
}

// ---- weight prep: transpose + bf16 hi/lo split for all 3 weights -----------
__global__ void k_wprep3(const float* __restrict__ W2, const float* __restrict__ W3,
                         const float* __restrict__ W4,
                         unsigned short* __restrict__ h2, unsigned short* __restrict__ l2,
                         unsigned short* __restrict__ h3, unsigned short* __restrict__ l3,
                         unsigned short* __restrict__ h4, unsigned short* __restrict__ l4) {
    int k = blockIdx.x, n = threadIdx.x;      // 512 x 512, y selects matrix
    const float* W = (blockIdx.y == 0) ? W2 : (blockIdx.y == 1) ? W3 : W4;
    unsigned short* hi = (blockIdx.y == 0) ? h2 : (blockIdx.y == 1) ? h3 : h4;
    unsigned short* lo = (blockIdx.y == 0) ? l2 : (blockIdx.y == 1) ? l3 : l4;
    float v = W[(size_t)k * G + n];
    __nv_bfloat16 h = __float2bfloat16_rn(v);
    float hf = __bfloat162float(h);
    __nv_bfloat16 l = __float2bfloat16_rn(v - hf);
    hi[(size_t)n * G + k] = __bfloat16_as_ushort(h);
    lo[(size_t)n * G + k] = __bfloat16_as_ushort(l);
}

// ---- main tcgen05 GEMM (warp-specialized 2-stage pipeline) ------------------
// MODE 0: A built from relu(Ai+Bj+Cq); MODE 1: A from planes; MODE 2: + fused mean
template<int MODE>
__global__ __launch_bounds__(THREADS, 2)
void k_mma(const unsigned short* __restrict__ aHi, const unsigned short* __restrict__ aLo,
           const unsigned short* __restrict__ wHi, const unsigned short* __restrict__ wLo,
           const float* __restrict__ bias,
           unsigned short* __restrict__ oHi, unsigned short* __restrict__ oLo) {
    extern __shared__ char smem[];
#if TC_OK
    const uint32_t sbase = smem_u32(smem);
    const int tid  = threadIdx.x;
    const int wid  = tid >> 5;
    const int lane = tid & 31;
    const int mBlk = blockIdx.x;              // 0..2047
    const int nBase = blockIdx.y * BN;        // 0 or 256
    float* sBias = (float*)(smem + S_BIAS);

    if (wid == 0) { TC_ALLOC(sbase + S_TMEM_O, 256); TC_RELINQ(); }
    if (tid == 0) {
        MBAR_INIT(sbase + S_FULL(0), 224); MBAR_INIT(sbase + S_FULL(1), 224);
        MBAR_INIT(sbase + S_FREE(0), 1);   MBAR_INIT(sbase + S_FREE(1), 1);
        MBAR_INIT(sbase + S_DONE, 1);
    }
    sBias[tid] = bias[nBase + tid];
    __syncthreads();
    uint32_t tmem;
    asm volatile("ld.shared.b32 %0, [%1];" : "=r"(tmem) : "r"(sbase + S_TMEM_O));

    if (wid >= 1) {
        // ================= LOADER warps (1..7, 224 threads) =================
        const int lt = tid - 32;
        for (int t = 0; t < TITER; ++t) {
            const int b = t & 1, kB = t * BK;
            if (t >= 2) mbar_wait(sbase + S_FREE(b), ((t - 2) >> 1) & 1);
            // ---- A tile: 128 rows x 32 k ----
            if (MODE == 0) {
                for (int idx = lt; idx < 512; idx += 224) {
                    int r = idx >> 2, u = idx & 3;     // 8 floats per unit
                    size_t gr = (size_t)mBlk * BM + r;
                    int n = (int)(gr >> 12), i = ((int)gr >> 6) & 63, j = (int)gr & 63;
                    size_t oA = ((size_t)(n * 64 + i)) * G + kB + u * 8;
                    size_t oB = ((size_t)(n * 64 + j)) * G + kB + u * 8;
                    size_t oQ = (size_t)n * G + kB + u * 8;
                    unsigned hw[4], lw[4];
                    #pragma unroll
                    for (int hh = 0; hh < 2; ++hh) {
                        float4 a4 = *(const float4*)&g_Ai[oA + hh * 4];
                        float4 b4 = *(const float4*)&g_Bj[oB + hh * 4];
                        float4 q4 = *(const float4*)&g_Cq[oQ + hh * 4];
                        float v0 = fmaxf(a4.x + b4.x + q4.x, 0.f);
                        float v1 = fmaxf(a4.y + b4.y + q4.y, 0.f);
                        float v2 = fmaxf(a4.z + b4.z + q4.z, 0.f);
                        float v3 = fmaxf(a4.w + b4.w + q4.w, 0.f);
                        split2(v0, v1, hw[hh*2],   lw[hh*2]);
                        split2(v2, v3, hw[hh*2+1], lw[hh*2+1]);
                    }
                    unsigned off = SWZ64((unsigned)(r * 64 + u * 16));
                    *(uint4*)(smem + ST_A_HI(b) + off) = make_uint4(hw[0],hw[1],hw[2],hw[3]);
                    *(uint4*)(smem + ST_A_LO(b) + off) = make_uint4(lw[0],lw[1],lw[2],lw[3]);
                }
            } else {
                for (int idx = lt; idx < 512; idx += 224) {
                    int r = idx >> 2, u = idx & 3;
                    size_t gsrc = ((size_t)mBlk * BM + r) * G + kB + u * 8;
                    unsigned off = SWZ64((unsigned)(r * 64 + u * 16));
                    CP16(sbase + ST_A_HI(b) + off, &aHi[gsrc]);
                    CP16(sbase + ST_A_LO(b) + off, &aLo[gsrc]);
                }
            }
            // ---- B tile: 256 rows x 32 k ----
            for (int idx = lt; idx < 1024; idx += 224) {
                int r = idx >> 2, u = idx & 3;
                size_t gsrc = (size_t)(nBase + r) * G + kB + u * 8;
                unsigned off = SWZ64((unsigned)(r * 64 + u * 16));
                CP16(sbase + ST_B_HI(b) + off, &wHi[gsrc]);
                CP16(sbase + ST_B_LO(b) + off, &wLo[gsrc]);
            }
            CP_COMMIT();
            CP_WAIT0();
            MBAR_ARRIVE(sbase + S_FULL(b));
        }
    } else if (elect_one()) {
        // ================= MMA issuer (1 thread of warp 0) ==================
        for (int t = 0; t < TITER; ++t) {
            const int b = t & 1;
            mbar_wait(sbase + S_FULL(b), (t >> 1) & 1);
            FENCE_ASYNC();
            uint64_t adH = MAKE_DESC64(sbase + ST_A_HI(b));
            uint64_t adL = MAKE_DESC64(sbase + ST_A_LO(b));
            uint64_t bdH = MAKE_DESC64(sbase + ST_B_HI(b));
            uint64_t bdL = MAKE_DESC64(sbase + ST_B_LO(b));
            #pragma unroll
            for (int s = 0; s < 2; ++s) {      // two K=16 chunks
                uint64_t o = (uint64_t)(s * 2);
                mma_bf16_ss(tmem, adH + o, bdH + o, MMA_IDESC, (t | s) ? 1u : 0u);
                mma_bf16_ss(tmem, adH + o, bdL + o, MMA_IDESC, 1u);
                mma_bf16_ss(tmem, adL + o, bdH + o, MMA_IDESC, 1u);
            }
            TC_COMMIT(sbase + S_FREE(b));
        }
        TC_COMMIT(sbase + S_DONE);
    }

    // all threads wait for the final MMA
    mbar_wait(sbase + S_DONE, 0);
    TC_FENCE_AFTER();

    // ---- epilogue ----
    float* sPart = (float*)(smem + ST_A_HI(0));   // [4][256] for MODE 2
    if (wid < 4) {
        int lrow = wid * 32 + lane;
        size_t grow = (size_t)mBlk * BM + lrow;
        #pragma unroll 1
        for (int c = 0; c < 8; ++c) {
            uint32_t r[32];
            TC_LD_X32(r, tmem + c * 32);
            TC_WAIT_LD();
            int cc = c * 32;
            if (MODE < 2) {
                #pragma unroll
                for (int q = 0; q < 4; ++q) {
                    unsigned hw[4], lw[4];
                    #pragma unroll
                    for (int e = 0; e < 4; ++e) {
                        float v0 = fmaxf(__uint_as_float(r[q*8+e*2])   + sBias[cc+q*8+e*2],   0.f);
                        float v1 = fmaxf(__uint_as_float(r[q*8+e*2+1]) + sBias[cc+q*8+e*2+1], 0.f);
                        split2(v0, v1, hw[e], lw[e]);
                    }
                    size_t go = grow * G + nBase + cc + q * 8;
                    *(uint4*)&oHi[go] = make_uint4(hw[0], hw[1], hw[2], hw[3]);
                    *(uint4*)&oLo[go] = make_uint4(lw[0], lw[1], lw[2], lw[3]);
                }
            } else {
                #pragma unroll
                for (int j = 0; j < 32; ++j) {
                    float v = fmaxf(__uint_as_float(r[j]) + sBias[cc + j], 0.f);
                    #pragma unroll
                    for (int o = 16; o > 0; o >>= 1)
                        v += __shfl_xor_sync(0xFFFFFFFFu, v, o);
                    if (lane == 0) sPart[wid * 256 + cc + j] = v;
                }
            }
        }
    }
    __syncthreads();
    if (MODE == 2) {
        float s = sPart[tid] + sPart[256 + tid] + sPart[512 + tid] + sPart[768 + tid];
        g_part[(size_t)mBlk * G + nBase + tid] = s;
        __syncthreads();
    }
    if (tid == 0) {
        MBAR_INVAL(sbase + S_FULL(0)); MBAR_INVAL(sbase + S_FULL(1));
        MBAR_INVAL(sbase + S_FREE(0)); MBAR_INVAL(sbase + S_FREE(1));
        MBAR_INVAL(sbase + S_DONE);
    }
    __syncthreads();
    if (wid == 0) TC_DEALLOC(tmem, 256);
#else
    // -------- scalar fallback (non-sm_103a compile passes only) --------
    const int tid  = threadIdx.x;
    const int mBlk = blockIdx.x;
    const int nBase = blockIdx.y * BN;
    const int col = nBase + tid;
    float colsum = 0.f;
    for (int r = 0; r < BM; ++r) {
        size_t gr = (size_t)mBlk * BM + r;
        float acc = bias[col];
        int n = (int)(gr >> 12), i = ((int)gr >> 6) & 63, j = (int)gr & 63;
        for (int k = 0; k < G; ++k) {
            float a;
            if (MODE == 0) {
                float raw = fmaxf(g_Ai[((size_t)(n * 64 + i)) * G + k]
                                + g_Bj[((size_t)(n * 64 + j)) * G + k]
                                + g_Cq[(size_t)n * G + k], 0.f);
                unsigned hh, ll;
                split2(raw, 0.f, hh, ll);
                a = us2f((unsigned short)(hh & 0xFFFFu)) + us2f((unsigned short)(ll & 0xFFFFu));
            } else {
                a = us2f(aHi[gr * G + k]) + us2f(aLo[gr * G + k]);
            }
            float w = us2f(wHi[(size_t)col * G + k]) + us2f(wLo[(size_t)col * G + k]);
            acc = fmaf(a, w, acc);
        }
        float v = fmaxf(acc, 0.f);
        if (MODE < 2) {
            unsigned hh, ll;
            split2(v, 0.f, hh, ll);
            oHi[gr * G + col] = (unsigned short)(hh & 0xFFFFu);
            oLo[gr * G + col] = (unsigned short)(ll & 0xFFFFu);
        } else colsum += v;
    }
    if (MODE == 2) g_part[(size_t)mBlk * G + col] = colsum;
#endif
}

// ---- final mean over 4096 pairs --------------------------------------------
__global__ void k_reduce2() {
    int n = blockIdx.x, k = threadIdx.x;   // 64 x 512
    float s = 0.f;
    #pragma unroll
    for (int b = 0; b < 32; ++b)
        s += g_part[(size_t)(n * 32 + b) * G + k];
    g_ctx[n * G + k] = s * (1.0f / 4096.0f);
}

// ---- f-MLP + log_softmax ---------------------------------------------------
__global__ void k_fmlp(const float* __restrict__ fw1, const float* __restrict__ fb1,
                       const float* __restrict__ fw2, const float* __restrict__ fb2,
                       const float* __restrict__ fw3, const float* __restrict__ fb3,
                       float* __restrict__ out) {
    int n = blockIdx.x, tid = threadIdx.x;   // 512 threads
    __shared__ float x[G], y[G];
    __shared__ float sc[2];
    x[tid] = g_ctx[n * G + tid];
    __syncthreads();
    float s0 = fb1[tid], s1 = 0.f;
    #pragma unroll 8
    for (int c = 0; c < G; c += 2) {
        s0 = fmaf(x[c],     fw1[(size_t)c * G + tid], s0);
        s1 = fmaf(x[c + 1], fw1[(size_t)(c + 1) * G + tid], s1);
    }
    y[tid] = fmaxf(s0 + s1, 0.f);
    __syncthreads();
    s0 = fb2[tid]; s1 = 0.f;
    #pragma unroll 8
    for (int c = 0; c < G; c += 2) {
        s0 = fmaf(y[c],     fw2[(size_t)c * G + tid], s0);
        s1 = fmaf(y[c + 1], fw2[(size_t)(c + 1) * G + tid], s1);
    }
    x[tid] = fmaxf(s0 + s1, 0.f);
    __syncthreads();
    if (tid < 2) {
        float t = fb3[tid];
        for (int c = 0; c < G; ++c) t = fmaf(x[c], fw3[c * 2 + tid], t);
        sc[tid] = t;
    }
    __syncthreads();
    if (tid == 0) {
        float m = fmaxf(sc[0], sc[1]);
        float lse = m + logf(expf(sc[0] - m) + expf(sc[1] - m));
        out[n * 2 + 0] = sc[0] - lse;
        out[n * 2 + 1] = sc[1] - lse;
    }
}

// ----------------------------------------------------------------------------
extern "C" void kernel_launch(void* const* d_in, const int* in_sizes, int n_in,
                              void* d_out, int out_size) {
    const float* img  = (const float*)d_in[0];
    const float* ques = (const float*)d_in[1];
    const float* g_w1 = (const float*)d_in[2];
    const float* g_b1 = (const float*)d_in[3];
    const float* g_w2 = (const float*)d_in[4];
    const float* g_b2 = (const float*)d_in[5];
    const float* g_w3 = (const float*)d_in[6];
    const float* g_b3 = (const float*)d_in[7];
    const float* g_w4 = (const float*)d_in[8];
    const float* g_b4 = (const float*)d_in[9];
    const float* f_w1 = (const float*)d_in[10];
    const float* f_b1 = (const float*)d_in[11];
    const float* f_w2 = (const float*)d_in[12];
    const float* f_b2 = (const float*)d_in[13];
    const float* f_w3 = (const float*)d_in[14];
    const float* f_b3 = (const float*)d_in[15];
    float* out = (float*)d_out;

    cudaFuncSetAttribute(k_mma<0>, cudaFuncAttributeMaxDynamicSharedMemorySize, SMEM_SZ);
    cudaFuncSetAttribute(k_mma<1>, cudaFuncAttributeMaxDynamicSharedMemorySize, SMEM_SZ);
    cudaFuncSetAttribute(k_mma<2>, cudaFuncAttributeMaxDynamicSharedMemorySize, SMEM_SZ);

    unsigned short *w2h, *w2l, *w3h, *w3l, *w4h, *w4l, *h2h, *h2l, *h3h, *h3l;
    cudaGetSymbolAddress((void**)&w2h, g_w2h); cudaGetSymbolAddress((void**)&w2l, g_w2l);
    cudaGetSymbolAddress((void**)&w3h, g_w3h); cudaGetSymbolAddress((void**)&w3l, g_w3l);
    cudaGetSymbolAddress((void**)&w4h, g_w4h); cudaGetSymbolAddress((void**)&w4l, g_w4l);
    cudaGetSymbolAddress((void**)&h2h, g_h2h); cudaGetSymbolAddress((void**)&h2l, g_h2l);
    cudaGetSymbolAddress((void**)&h3h, g_h3h); cudaGetSymbolAddress((void**)&h3l, g_h3l);

    k_wprep3<<<dim3(G, 3), G>>>(g_w2, g_w3, g_w4, w2h, w2l, w3h, w3l, w4h, w4l);
    k_ab<<<dim3(NB, 8), 512>>>(img, g_w1);
    k_cq<<<NB, 512>>>(ques, g_w1, g_b1);

    dim3 gg(MROWS / BM, G / BN);   // 2048 x 2
    k_mma<0><<<gg, THREADS, SMEM_SZ>>>(nullptr, nullptr, w2h, w2l, g_b2, h2h, h2l);
    k_mma<1><<<gg, THREADS, SMEM_SZ>>>(h2h, h2l, w3h, w3l, g_b3, h3h, h3l);
    k_mma<2><<<gg, THREADS, SMEM_SZ>>>(h3h, h3l, w4h, w4l, g_b4, nullptr, nullptr);

    k_reduce2<<<NB, 512>>>();
    k_fmlp<<<NB, 512>>>(f_w1, f_b1, f_w2, f_b2, f_w3, f_b3, out);
}

// round 8
// speedup vs baseline: 1.3521x; 1.0612x over previous
#include <cuda_runtime.h>
#include <cuda.h>
#include <cuda_bf16.h>
#include <math.h>
#include <stdint.h>

// ----------------------------------------------------------------------------
// RelNet forward, tcgen05 sm_103a, bf16 hi/lo split GEMMs, TMA-fed pipeline
// N=64, C=64, H=W=8 (HW=64), E=256, G=512, GIN=388
// ----------------------------------------------------------------------------

#if defined(__CUDA_ARCH__) && (defined(__CUDA_ARCH_FEAT_SM103_ALL) || \
    defined(__CUDA_ARCH_FEAT_SM100_ALL) || defined(__CUDA_ARCH_FEAT_SM101_ALL))
#define TC_OK 1
#else
#define TC_OK 0
#endif

#define NB   64
#define HW   64
#define FDIM 66
#define G    512
#define E    256
#define MROWS (NB * HW * HW)   // 262144

#define BM 128
#define BN 256
#define BK 32
#define TITER (G / BK)         // 16 pipeline iterations
#define THREADS 256

// SMEM control block + 2 stages of (Ahi8K|Alo8K|Bhi16K|Blo16K) = 48KB each
#define S_TMEM_O  0
#define S_FULL(b) (8 + (b) * 8)      // 8, 16
#define S_FREE(b) (24 + (b) * 8)     // 24, 32
#define S_DONE    40
#define S_BIAS    64                 // 256 floats
#define STAGE_SZ  49152
#define ST_A_HI(b) (2048 + (b) * STAGE_SZ)
#define ST_A_LO(b) (ST_A_HI(b) + 8192)
#define ST_B_HI(b) (ST_A_HI(b) + 16384)
#define ST_B_LO(b) (ST_A_HI(b) + 32768)
#define SMEM_SZ    (2048 + 2 * STAGE_SZ)   // 100352 -> 2 CTAs/SM

// idesc: kind::f16, dtype=F32, atype=BF16, btype=BF16, N=256, M=128
#define MMA_IDESC ((1u<<4)|(1u<<7)|(1u<<10)|(32u<<17)|(8u<<24))

// SW64 K-major descriptor (layout=4, version=1, SBO=32, LBO=1); 64B rows
#define SMEM_DESC_BASE_SW64 \
    ((uint64_t(4)<<61)|(uint64_t(1)<<46)|(uint64_t(32)<<32)|(uint64_t(1)<<16))
#define MAKE_DESC64(a) (SMEM_DESC_BASE_SW64 | ((uint64_t)((a) >> 4) & 0x3FFF))
#define SWZ64(o) ((o) ^ (((o) >> 3) & 0x30))

// ---------------- device scratch (separate hi/lo planes) ----------------
__device__ unsigned short g_h2h[(size_t)MROWS * G], g_h2l[(size_t)MROWS * G];
__device__ unsigned short g_h3h[(size_t)MROWS * G], g_h3l[(size_t)MROWS * G];
__device__ float          g_Ai[(size_t)NB * HW * G];
__device__ float          g_Bj[(size_t)NB * HW * G];
__device__ float          g_Cq[NB * G];
__device__ float          g_part[(size_t)(MROWS / BM) * G];  // 2048 x 512
__device__ float          g_ctx[NB * G];
__device__ unsigned short g_w2h[G * G], g_w2l[G * G];
__device__ unsigned short g_w3h[G * G], g_w3l[G * G];
__device__ unsigned short g_w4h[G * G], g_w4l[G * G];

// ---------------- generic helpers ----------------
__device__ __forceinline__ void split2(float v0, float v1, unsigned &hi, unsigned &lo) {
    __nv_bfloat16 h0 = __float2bfloat16_rn(v0), h1 = __float2bfloat16_rn(v1);
    float l0f = v0 - __bfloat162float(h0), l1f = v1 - __bfloat162float(h1);
    __nv_bfloat16 l0 = __float2bfloat16_rn(l0f), l1 = __float2bfloat16_rn(l1f);
    hi = (unsigned)__bfloat16_as_ushort(h0) | ((unsigned)__bfloat16_as_ushort(h1) << 16);
    lo = (unsigned)__bfloat16_as_ushort(l0) | ((unsigned)__bfloat16_as_ushort(l1) << 16);
}
__device__ __forceinline__ float us2f(unsigned short u) {
    return __bfloat162float(__ushort_as_bfloat16(u));
}

#if TC_OK
// ---------------- tcgen05 / async PTX helpers (sm_103a only) ----------------
__device__ __forceinline__ uint32_t smem_u32(const void* p) {
    uint32_t a;
    asm("{ .reg .u64 t; cvta.to.shared.u64 t, %1; cvt.u32.u64 %0, t; }"
        : "=r"(a) : "l"(p));
    return a;
}
__device__ __forceinline__ void mma_bf16_ss(uint32_t d, uint64_t ad, uint64_t bd,
                                            uint32_t idesc, uint32_t en) {
    asm volatile(
        "{\n\t.reg .pred p;\n\tsetp.ne.u32 p, %4, 0;\n\t"
        "tcgen05.mma.cta_group::1.kind::f16 [%0], %1, %2, %3, {%5,%5,%5,%5}, p;\n\t}"
        :: "r"(d), "l"(ad), "l"(bd), "r"(idesc), "r"(en), "r"(0u) : "memory");
}
#define TC_ALLOC(sp, n)  asm volatile("tcgen05.alloc.cta_group::1.sync.aligned.shared::cta.b32 [%0], %1;" :: "r"(sp), "r"(n) : "memory")
#define TC_RELINQ()      asm volatile("tcgen05.relinquish_alloc_permit.cta_group::1.sync.aligned;")
#define TC_DEALLOC(t, n) asm volatile("tcgen05.dealloc.cta_group::1.sync.aligned.b32 %0, %1;" :: "r"(t), "r"(n))
#define TC_COMMIT(mb)    asm volatile("tcgen05.commit.cta_group::1.mbarrier::arrive::one.shared::cluster.b64 [%0];" :: "r"(mb) : "memory")
#define TC_FENCE_AFTER() asm volatile("tcgen05.fence::after_thread_sync;" ::: "memory")
#define TC_WAIT_LD()     asm volatile("tcgen05.wait::ld.sync.aligned;" ::: "memory")
#define FENCE_ASYNC()    asm volatile("fence.proxy.async.shared::cta;" ::: "memory")
#define MBAR_INIT(mb, c) asm volatile("mbarrier.init.shared.b64 [%0], %1;" :: "r"(mb), "r"(c) : "memory")
#define MBAR_INVAL(mb)   asm volatile("mbarrier.inval.shared.b64 [%0];" :: "r"(mb) : "memory")
#define MBAR_ARRIVE(mb)  asm volatile("mbarrier.arrive.release.cta.shared::cta.b64 _, [%0];" :: "r"(mb) : "memory")
#define MBAR_EXPECT_TX(mb, n) asm volatile("mbarrier.arrive.expect_tx.shared.b64 _, [%0], %1;" :: "r"(mb), "r"((uint32_t)(n)) : "memory")
#define TMA2D(dst, map, x, y, mb) \
    asm volatile("cp.async.bulk.tensor.2d.shared::cta.global.tile.mbarrier::complete_tx::bytes " \
                 "[%0], [%1, {%2, %3}], [%4];" \
                 :: "r"(dst), "l"(map), "r"(x), "r"(y), "r"(mb) : "memory")

__device__ __forceinline__ void mbar_wait(uint32_t mb, uint32_t parity) {
    asm volatile(
        "{\n\t.reg .pred P;\n\t"
        "WL_%=:\n\t"
        "mbarrier.try_wait.parity.acquire.cta.shared::cta.b64 P, [%0], %1, 0x989680;\n\t"
        "@P bra.uni WD_%=;\n\t"
        "bra.uni WL_%=;\n\t"
        "WD_%=:\n\t}"
        :: "r"(mb), "r"(parity) : "memory");
}
#define TC_LD_X32(r, a) \
    asm volatile("tcgen05.ld.sync.aligned.32x32b.x32.b32 " \
        "{%0,%1,%2,%3,%4,%5,%6,%7,%8,%9,%10,%11,%12,%13,%14,%15," \
        "%16,%17,%18,%19,%20,%21,%22,%23,%24,%25,%26,%27,%28,%29,%30,%31}, [%32];" \
        : "=r"((r)[0]),"=r"((r)[1]),"=r"((r)[2]),"=r"((r)[3]), \
          "=r"((r)[4]),"=r"((r)[5]),"=r"((r)[6]),"=r"((r)[7]), \
          "=r"((r)[8]),"=r"((r)[9]),"=r"((r)[10]),"=r"((r)[11]), \
          "=r"((r)[12]),"=r"((r)[13]),"=r"((r)[14]),"=r"((r)[15]), \
          "=r"((r)[16]),"=r"((r)[17]),"=r"((r)[18]),"=r"((r)[19]), \
          "=r"((r)[20]),"=r"((r)[21]),"=r"((r)[22]),"=r"((r)[23]), \
          "=r"((r)[24]),"=r"((r)[25]),"=r"((r)[26]),"=r"((r)[27]), \
          "=r"((r)[28]),"=r"((r)[29]),"=r"((r)[30]),"=r"((r)[31]) \
        : "r"(a))
#endif  // TC_OK

// ---- K1: Ai = feat_i @ W1a, Bj = feat_j @ W1b (8 positions per block) ------
__global__ void k_ab(const float* __restrict__ img, const float* __restrict__ w1) {
    int n = blockIdx.x, pg = blockIdx.y;     // 64 x 8
    int tid = threadIdx.x;                   // 512
    __shared__ float f[8][FDIM];
    if (tid < 64) {
        int c = tid;
        #pragma unroll
        for (int p8 = 0; p8 < 8; ++p8)
            f[p8][c] = img[((size_t)n * 64 + c) * 64 + pg * 8 + p8];
    } else if (tid < 72) {
        int p8 = tid - 64, p = pg * 8 + p8;
        f[p8][64] = (float)(p >> 3);
        f[p8][65] = (float)(p & 7);
    }
    __syncthreads();
    float a[8] = {0,0,0,0,0,0,0,0}, b[8] = {0,0,0,0,0,0,0,0};
    #pragma unroll 2
    for (int c = 0; c < FDIM; ++c) {
        float wa = w1[(size_t)c * G + tid];
        float wb = w1[(size_t)(c + FDIM) * G + tid];
        #pragma unroll
        for (int p8 = 0; p8 < 8; ++p8) {
            a[p8] = fmaf(f[p8][c], wa, a[p8]);
            b[p8] = fmaf(f[p8][c], wb, b[p8]);
        }
    }
    #pragma unroll
    for (int p8 = 0; p8 < 8; ++p8) {
        int row = n * 64 + pg * 8 + p8;
        g_Ai[(size_t)row * G + tid] = a[p8];
        g_Bj[(size_t)row * G + tid] = b[p8];
    }
}

// ---- K2: Cq = ques @ W1c + b1 ----------------------------------------------
__global__ void k_cq(const float* __restrict__ ques, const float* __restrict__ w1,
                     const float* __restrict__ b1) {
    int n = blockIdx.x, tid = threadIdx.x;    // 512 threads
    __shared__ float q[E];
    if (tid < E) q[tid] = ques[n * E + tid];
    __syncthreads();
    float s0 = b1[tid], s1 = 0.f;
    #pragma unroll 8
    for (int e = 0; e < E; e += 2) {
        s0 = fmaf(q[e],     w1[(size_t)(2 * FDIM + e) * G + tid], s0);
        s1 = fmaf(q[e + 1], w1[(size_t)(2 * FDIM + e + 1) * G + tid], s1);
    }
    g_Cq[n * G + tid] = s0 + s1;
}

// ---- weight prep: transpose + bf16 hi/lo split for all 3 weights -----------
__global__ void k_wprep3(const float* __restrict__ W2, const float* __restrict__ W3,
                         const float* __restrict__ W4,
                         unsigned short* __restrict__ h2, unsigned short* __restrict__ l2,
                         unsigned short* __restrict__ h3, unsigned short* __restrict__ l3,
                         unsigned short* __restrict__ h4, unsigned short* __restrict__ l4) {
    int k = blockIdx.x, n = threadIdx.x;      // 512 x 512, y selects matrix
    const float* W = (blockIdx.y == 0) ? W2 : (blockIdx.y == 1) ? W3 : W4;
    unsigned short* hi = (blockIdx.y == 0) ? h2 : (blockIdx.y == 1) ? h3 : h4;
    unsigned short* lo = (blockIdx.y == 0) ? l2 : (blockIdx.y == 1) ? l3 : l4;
    float v = W[(size_t)k * G + n];
    __nv_bfloat16 h = __float2bfloat16_rn(v);
    float hf = __bfloat162float(h);
    __nv_bfloat16 l = __float2bfloat16_rn(v - hf);
    hi[(size_t)n * G + k] = __bfloat16_as_ushort(h);
    lo[(size_t)n * G + k] = __bfloat16_as_ushort(l);
}

// ---- main tcgen05 GEMM, TMA-fed warp-specialized 2-stage pipeline ----------
// MODE 0: A generated by warps 2-7 from relu(Ai+Bj+Cq); B via TMA
// MODE 1: A and B via TMA; MODE 2: same + fused mean epilogue
template<int MODE>
__global__ __launch_bounds__(THREADS, 2)
void k_mma(const __grid_constant__ CUtensorMap tmAh,
           const __grid_constant__ CUtensorMap tmAl,
           const __grid_constant__ CUtensorMap tmBh,
           const __grid_constant__ CUtensorMap tmBl,
           const float* __restrict__ bias,
           unsigned short* __restrict__ oHi, unsigned short* __restrict__ oLo,
           const unsigned short* __restrict__ aHi, const unsigned short* __restrict__ aLo,
           const unsigned short* __restrict__ wHi, const unsigned short* __restrict__ wLo) {
    extern __shared__ char smem[];
#if TC_OK
    const uint32_t sbase = smem_u32(smem);
    const int tid  = threadIdx.x;
    const int wid  = tid >> 5;
    const int lane = tid & 31;
    const int mBlk = blockIdx.x;              // 0..2047
    const int nBase = blockIdx.y * BN;        // 0 or 256
    float* sBias = (float*)(smem + S_BIAS);

    const unsigned fullCnt = (MODE == 0) ? 193u : 1u;   // producers arriving on FULL
    const unsigned txBytes = (MODE == 0) ? 32768u : 49152u;

    if (wid == 0) { TC_ALLOC(sbase + S_TMEM_O, 256); TC_RELINQ(); }
    if (tid == 0) {
        MBAR_INIT(sbase + S_FULL(0), fullCnt); MBAR_INIT(sbase + S_FULL(1), fullCnt);
        MBAR_INIT(sbase + S_FREE(0), 1);       MBAR_INIT(sbase + S_FREE(1), 1);
        MBAR_INIT(sbase + S_DONE, 1);
    }
    sBias[tid] = bias[nBase + tid];
    __syncthreads();
    uint32_t tmem;
    asm volatile("ld.shared.b32 %0, [%1];" : "=r"(tmem) : "r"(sbase + S_TMEM_O));

    if (tid == 32) {
        // ================= TMA producer (single thread) =====================
        for (int t = 0; t < TITER; ++t) {
            const int b = t & 1, kB = t * BK;
            if (t >= 2) mbar_wait(sbase + S_FREE(b), ((t - 2) >> 1) & 1);
            MBAR_EXPECT_TX(sbase + S_FULL(b), txBytes);
            if (MODE != 0) {
                TMA2D(sbase + ST_A_HI(b), &tmAh, kB, mBlk * BM, sbase + S_FULL(b));
                TMA2D(sbase + ST_A_LO(b), &tmAl, kB, mBlk * BM, sbase + S_FULL(b));
            }
            TMA2D(sbase + ST_B_HI(b), &tmBh, kB, nBase, sbase + S_FULL(b));
            TMA2D(sbase + ST_B_LO(b), &tmBl, kB, nBase, sbase + S_FULL(b));
        }
    } else if (MODE == 0 && tid >= 64) {
        // ================= A-tile builders (warps 2-7, 192 thr) =============
        for (int t = 0; t < TITER; ++t) {
            const int b = t & 1, kB = t * BK;
            if (t >= 2) mbar_wait(sbase + S_FREE(b), ((t - 2) >> 1) & 1);
            for (int idx = tid - 64; idx < 512; idx += 192) {
                int r = idx >> 2, u = idx & 3;     // 8 floats per unit
                size_t gr = (size_t)mBlk * BM + r;
                int n = (int)(gr >> 12), i = ((int)gr >> 6) & 63, j = (int)gr & 63;
                size_t oA = ((size_t)(n * 64 + i)) * G + kB + u * 8;
                size_t oB = ((size_t)(n * 64 + j)) * G + kB + u * 8;
                size_t oQ = (size_t)n * G + kB + u * 8;
                unsigned hw[4], lw[4];
                #pragma unroll
                for (int hh = 0; hh < 2; ++hh) {
                    float4 a4 = *(const float4*)&g_Ai[oA + hh * 4];
                    float4 b4 = *(const float4*)&g_Bj[oB + hh * 4];
                    float4 q4 = *(const float4*)&g_Cq[oQ + hh * 4];
                    float v0 = fmaxf(a4.x + b4.x + q4.x, 0.f);
                    float v1 = fmaxf(a4.y + b4.y + q4.y, 0.f);
                    float v2 = fmaxf(a4.z + b4.z + q4.z, 0.f);
                    float v3 = fmaxf(a4.w + b4.w + q4.w, 0.f);
                    split2(v0, v1, hw[hh*2],   lw[hh*2]);
                    split2(v2, v3, hw[hh*2+1], lw[hh*2+1]);
                }
                unsigned off = SWZ64((unsigned)(r * 64 + u * 16));
                *(uint4*)(smem + ST_A_HI(b) + off) = make_uint4(hw[0],hw[1],hw[2],hw[3]);
                *(uint4*)(smem + ST_A_LO(b) + off) = make_uint4(lw[0],lw[1],lw[2],lw[3]);
            }
            FENCE_ASYNC();
            MBAR_ARRIVE(sbase + S_FULL(b));
        }
    } else if (tid == 0) {
        // ================= MMA issuer (single thread) =======================
        for (int t = 0; t < TITER; ++t) {
            const int b = t & 1;
            mbar_wait(sbase + S_FULL(b), (t >> 1) & 1);
            FENCE_ASYNC();
            uint64_t adH = MAKE_DESC64(sbase + ST_A_HI(b));
            uint64_t adL = MAKE_DESC64(sbase + ST_A_LO(b));
            uint64_t bdH = MAKE_DESC64(sbase + ST_B_HI(b));
            uint64_t bdL = MAKE_DESC64(sbase + ST_B_LO(b));
            #pragma unroll
            for (int s = 0; s < 2; ++s) {      // two K=16 chunks
                uint64_t o = (uint64_t)(s * 2);
                mma_bf16_ss(tmem, adH + o, bdH + o, MMA_IDESC, (t | s) ? 1u : 0u);
                mma_bf16_ss(tmem, adH + o, bdL + o, MMA_IDESC, 1u);
                mma_bf16_ss(tmem, adL + o, bdH + o, MMA_IDESC, 1u);
            }
            TC_COMMIT(sbase + S_FREE(b));
        }
        TC_COMMIT(sbase + S_DONE);
    }

    // all threads wait for the final MMA
    mbar_wait(sbase + S_DONE, 0);
    TC_FENCE_AFTER();

    // ---- epilogue ----
    float* sPart = (float*)(smem + ST_A_HI(0));   // [4][256] for MODE 2
    if (wid < 4) {
        int lrow = wid * 32 + lane;
        size_t grow = (size_t)mBlk * BM + lrow;
        #pragma unroll 1
        for (int c = 0; c < 8; ++c) {
            uint32_t r[32];
            TC_LD_X32(r, tmem + c * 32);
            TC_WAIT_LD();
            int cc = c * 32;
            if (MODE < 2) {
                #pragma unroll
                for (int q = 0; q < 4; ++q) {
                    unsigned hw[4], lw[4];
                    #pragma unroll
                    for (int e = 0; e < 4; ++e) {
                        float v0 = fmaxf(__uint_as_float(r[q*8+e*2])   + sBias[cc+q*8+e*2],   0.f);
                        float v1 = fmaxf(__uint_as_float(r[q*8+e*2+1]) + sBias[cc+q*8+e*2+1], 0.f);
                        split2(v0, v1, hw[e], lw[e]);
                    }
                    size_t go = grow * G + nBase + cc + q * 8;
                    *(uint4*)&oHi[go] = make_uint4(hw[0], hw[1], hw[2], hw[3]);
                    *(uint4*)&oLo[go] = make_uint4(lw[0], lw[1], lw[2], lw[3]);
                }
            } else {
                #pragma unroll
                for (int j = 0; j < 32; ++j) {
                    float v = fmaxf(__uint_as_float(r[j]) + sBias[cc + j], 0.f);
                    #pragma unroll
                    for (int o = 16; o > 0; o >>= 1)
                        v += __shfl_xor_sync(0xFFFFFFFFu, v, o);
                    if (lane == 0) sPart[wid * 256 + cc + j] = v;
                }
            }
        }
    }
    __syncthreads();
    if (MODE == 2) {
        float s = sPart[tid] + sPart[256 + tid] + sPart[512 + tid] + sPart[768 + tid];
        g_part[(size_t)mBlk * G + nBase + tid] = s;
        __syncthreads();
    }
    if (tid == 0) {
        MBAR_INVAL(sbase + S_FULL(0)); MBAR_INVAL(sbase + S_FULL(1));
        MBAR_INVAL(sbase + S_FREE(0)); MBAR_INVAL(sbase + S_FREE(1));
        MBAR_INVAL(sbase + S_DONE);
    }
    __syncthreads();
    if (wid == 0) TC_DEALLOC(tmem, 256);
#else
    // -------- scalar fallback (non-sm_103a compile passes only) --------
    const int tid  = threadIdx.x;
    const int mBlk = blockIdx.x;
    const int nBase = blockIdx.y * BN;
    const int col = nBase + tid;
    float colsum = 0.f;
    for (int r = 0; r < BM; ++r) {
        size_t gr = (size_t)mBlk * BM + r;
        float acc = bias[col];
        int n = (int)(gr >> 12), i = ((int)gr >> 6) & 63, j = (int)gr & 63;
        for (int k = 0; k < G; ++k) {
            float a;
            if (MODE == 0) {
                float raw = fmaxf(g_Ai[((size_t)(n * 64 + i)) * G + k]
                                + g_Bj[((size_t)(n * 64 + j)) * G + k]
                                + g_Cq[(size_t)n * G + k], 0.f);
                unsigned hh, ll;
                split2(raw, 0.f, hh, ll);
                a = us2f((unsigned short)(hh & 0xFFFFu)) + us2f((unsigned short)(ll & 0xFFFFu));
            } else {
                a = us2f(aHi[gr * G + k]) + us2f(aLo[gr * G + k]);
            }
            float w = us2f(wHi[(size_t)col * G + k]) + us2f(wLo[(size_t)col * G + k]);
            acc = fmaf(a, w, acc);
        }
        float v = fmaxf(acc, 0.f);
        if (MODE < 2) {
            unsigned hh, ll;
            split2(v, 0.f, hh, ll);
            oHi[gr * G + col] = (unsigned short)(hh & 0xFFFFu);
            oLo[gr * G + col] = (unsigned short)(ll & 0xFFFFu);
        } else colsum += v;
    }
    if (MODE == 2) g_part[(size_t)mBlk * G + col] = colsum;
#endif
}

// ---- final mean over 4096 pairs --------------------------------------------
__global__ void k_reduce2() {
    int n = blockIdx.x, k = threadIdx.x;   // 64 x 512
    float s = 0.f;
    #pragma unroll
    for (int b = 0; b < 32; ++b)
        s += g_part[(size_t)(n * 32 + b) * G + k];
    g_ctx[n * G + k] = s * (1.0f / 4096.0f);
}

// ---- f-MLP + log_softmax ---------------------------------------------------
__global__ void k_fmlp(const float* __restrict__ fw1, const float* __restrict__ fb1,
                       const float* __restrict__ fw2, const float* __restrict__ fb2,
                       const float* __restrict__ fw3, const float* __restrict__ fb3,
                       float* __restrict__ out) {
    int n = blockIdx.x, tid = threadIdx.x;   // 512 threads
    __shared__ float x[G], y[G];
    __shared__ float sc[2];
    x[tid] = g_ctx[n * G + tid];
    __syncthreads();
    float s0 = fb1[tid], s1 = 0.f;
    #pragma unroll 8
    for (int c = 0; c < G; c += 2) {
        s0 = fmaf(x[c],     fw1[(size_t)c * G + tid], s0);
        s1 = fmaf(x[c + 1], fw1[(size_t)(c + 1) * G + tid], s1);
    }
    y[tid] = fmaxf(s0 + s1, 0.f);
    __syncthreads();
    s0 = fb2[tid]; s1 = 0.f;
    #pragma unroll 8
    for (int c = 0; c < G; c += 2) {
        s0 = fmaf(y[c],     fw2[(size_t)c * G + tid], s0);
        s1 = fmaf(y[c + 1], fw2[(size_t)(c + 1) * G + tid], s1);
    }
    x[tid] = fmaxf(s0 + s1, 0.f);
    __syncthreads();
    if (tid < 2) {
        float t = fb3[tid];
        for (int c = 0; c < G; ++c) t = fmaf(x[c], fw3[c * 2 + tid], t);
        sc[tid] = t;
    }
    __syncthreads();
    if (tid == 0) {
        float m = fmaxf(sc[0], sc[1]);
        float lse = m + logf(expf(sc[0] - m) + expf(sc[1] - m));
        out[n * 2 + 0] = sc[0] - lse;
        out[n * 2 + 1] = sc[1] - lse;
    }
}

// ---------------- host: tensormap building ----------------
typedef CUresult (*EncodeFn)(CUtensorMap*, CUtensorMapDataType, cuuint32_t, void*,
                             const cuuint64_t*, const cuuint64_t*, const cuuint32_t*,
                             const cuuint32_t*, CUtensorMapInterleave, CUtensorMapSwizzle,
                             CUtensorMapL2promotion, CUtensorMapFloatOOBfill);

static EncodeFn get_encoder() {
    void* fn = nullptr;
    cudaDriverEntryPointQueryResult st;
    cudaGetDriverEntryPoint("cuTensorMapEncodeTiled", &fn, cudaEnableDefault, &st);
    return (EncodeFn)fn;
}
static void build_map(EncodeFn enc, CUtensorMap* m, void* base,
                      unsigned long long rows, unsigned boxRows) {
    cuuint64_t dims[2]    = {(cuuint64_t)G, (cuuint64_t)rows};
    cuuint64_t strides[1] = {(cuuint64_t)G * 2};   // bf16 bytes
    cuuint32_t box[2]     = {(cuuint32_t)BK, (cuuint32_t)boxRows};
    cuuint32_t es[2]      = {1, 1};
    enc(m, CU_TENSOR_MAP_DATA_TYPE_BFLOAT16, 2, base, dims, strides, box, es,
        CU_TENSOR_MAP_INTERLEAVE_NONE, CU_TENSOR_MAP_SWIZZLE_64B,
        CU_TENSOR_MAP_L2_PROMOTION_L2_128B, CU_TENSOR_MAP_FLOAT_OOB_FILL_NONE);
}

// ----------------------------------------------------------------------------
extern "C" void kernel_launch(void* const* d_in, const int* in_sizes, int n_in,
                              void* d_out, int out_size) {
    const float* img  = (const float*)d_in[0];
    const float* ques = (const float*)d_in[1];
    const float* g_w1 = (const float*)d_in[2];
    const float* g_b1 = (const float*)d_in[3];
    const float* g_w2 = (const float*)d_in[4];
    const float* g_b2 = (const float*)d_in[5];
    const float* g_w3 = (const float*)d_in[6];
    const float* g_b3 = (const float*)d_in[7];
    const float* g_w4 = (const float*)d_in[8];
    const float* g_b4 = (const float*)d_in[9];
    const float* f_w1 = (const float*)d_in[10];
    const float* f_b1 = (const float*)d_in[11];
    const float* f_w2 = (const float*)d_in[12];
    const float* f_b2 = (const float*)d_in[13];
    const float* f_w3 = (const float*)d_in[14];
    const float* f_b3 = (const float*)d_in[15];
    float* out = (float*)d_out;

    cudaFuncSetAttribute(k_mma<0>, cudaFuncAttributeMaxDynamicSharedMemorySize, SMEM_SZ);
    cudaFuncSetAttribute(k_mma<1>, cudaFuncAttributeMaxDynamicSharedMemorySize, SMEM_SZ);
    cudaFuncSetAttribute(k_mma<2>, cudaFuncAttributeMaxDynamicSharedMemorySize, SMEM_SZ);

    unsigned short *w2h, *w2l, *w3h, *w3l, *w4h, *w4l, *h2h, *h2l, *h3h, *h3l;
    cudaGetSymbolAddress((void**)&w2h, g_w2h); cudaGetSymbolAddress((void**)&w2l, g_w2l);
    cudaGetSymbolAddress((void**)&w3h, g_w3h); cudaGetSymbolAddress((void**)&w3l, g_w3l);
    cudaGetSymbolAddress((void**)&w4h, g_w4h); cudaGetSymbolAddress((void**)&w4l, g_w4l);
    cudaGetSymbolAddress((void**)&h2h, g_h2h); cudaGetSymbolAddress((void**)&h2l, g_h2l);
    cudaGetSymbolAddress((void**)&h3h, g_h3h); cudaGetSymbolAddress((void**)&h3l, g_h3l);

    EncodeFn enc = get_encoder();
    CUtensorMap mW2h, mW2l, mW3h, mW3l, mW4h, mW4l, mA2h, mA2l, mA3h, mA3l;
    build_map(enc, &mW2h, w2h, G, BN);       build_map(enc, &mW2l, w2l, G, BN);
    build_map(enc, &mW3h, w3h, G, BN);       build_map(enc, &mW3l, w3l, G, BN);
    build_map(enc, &mW4h, w4h, G, BN);       build_map(enc, &mW4l, w4l, G, BN);
    build_map(enc, &mA2h, h2h, MROWS, BM);   build_map(enc, &mA2l, h2l, MROWS, BM);
    build_map(enc, &mA3h, h3h, MROWS, BM);   build_map(enc, &mA3l, h3l, MROWS, BM);

    k_wprep3<<<dim3(G, 3), G>>>(g_w2, g_w3, g_w4, w2h, w2l, w3h, w3l, w4h, w4l);
    k_ab<<<dim3(NB, 8), 512>>>(img, g_w1);
    k_cq<<<NB, 512>>>(ques, g_w1, g_b1);

    dim3 gg(MROWS / BM, G / BN);   // 2048 x 2
    k_mma<0><<<gg, THREADS, SMEM_SZ>>>(mW2h, mW2l, mW2h, mW2l, g_b2, h2h, h2l,
                                       nullptr, nullptr, w2h, w2l);
    k_mma<1><<<gg, THREADS, SMEM_SZ>>>(mA2h, mA2l, mW3h, mW3l, g_b3, h3h, h3l,
                                       h2h, h2l, w3h, w3l);
    k_mma<2><<<gg, THREADS, SMEM_SZ>>>(mA3h, mA3l, mW4h, mW4l, g_b4, nullptr, nullptr,
                                       h3h, h3l, w4h, w4l);

    k_reduce2<<<NB, 512>>>();
    k_fmlp<<<NB, 512>>>(f_w1, f_b1, f_w2, f_b2, f_w3, f_b3, out);
}

// round 9
// speedup vs baseline: 1.3664x; 1.0105x over previous
#include <cuda_runtime.h>
#include <cuda.h>
#include <cuda_bf16.h>
#include <math.h>
#include <stdint.h>

// ----------------------------------------------------------------------------
// RelNet forward, tcgen05 sm_103a, bf16 hi/lo split GEMMs.
// BM=256 x BN=256 tiles, TMEM 512 (2 D accumulators), 3-stage TMA ring.
// ----------------------------------------------------------------------------

#if defined(__CUDA_ARCH__) && (defined(__CUDA_ARCH_FEAT_SM103_ALL) || \
    defined(__CUDA_ARCH_FEAT_SM100_ALL) || defined(__CUDA_ARCH_FEAT_SM101_ALL))
#define TC_OK 1
#else
#define TC_OK 0
#endif

#define NB   64
#define HW   64
#define FDIM 66
#define G    512
#define E    256
#define MROWS (NB * HW * HW)   // 262144

#define BM 256
#define BN 256
#define BK 32
#define TITER (G / BK)         // 16
#define NSTAGE 3
#define THREADS 512
#define MBLKS (MROWS / BM)     // 1024

// SMEM: 4KB ctrl + 3 stages x 64KB
#define S_TMEM_O  0
#define S_FULL(b) (8 + (b) * 8)      // 8..24
#define S_FREE(b) (32 + (b) * 8)     // 32..48
#define S_DONE    56
#define S_BIAS    64                 // 256 floats -> ends 1088
#define STAGE_SZ  65536
#define ST_A_HI(b) (4096 + (b) * STAGE_SZ)
#define ST_A_LO(b) (ST_A_HI(b) + 16384)
#define ST_B_HI(b) (ST_A_HI(b) + 32768)
#define ST_B_LO(b) (ST_A_HI(b) + 49152)
#define SMEM_SZ    (4096 + NSTAGE * STAGE_SZ)   // 200704 -> 1 CTA/SM

// idesc: kind::f16, dtype=F32, atype=BF16, btype=BF16, N=256, M=128
#define MMA_IDESC ((1u<<4)|(1u<<7)|(1u<<10)|(32u<<17)|(8u<<24))

// SW64 K-major descriptor (layout=4, version=1, SBO=32, LBO=1); 64B rows
#define SMEM_DESC_BASE_SW64 \
    ((uint64_t(4)<<61)|(uint64_t(1)<<46)|(uint64_t(32)<<32)|(uint64_t(1)<<16))
#define MAKE_DESC64(a) (SMEM_DESC_BASE_SW64 | ((uint64_t)((a) >> 4) & 0x3FFF))
#define SWZ64(o) ((o) ^ (((o) >> 3) & 0x30))

// ---------------- device scratch (separate hi/lo planes) ----------------
__device__ unsigned short g_h2h[(size_t)MROWS * G], g_h2l[(size_t)MROWS * G];
__device__ unsigned short g_h3h[(size_t)MROWS * G], g_h3l[(size_t)MROWS * G];
__device__ float          g_Ai[(size_t)NB * HW * G];
__device__ float          g_Bj[(size_t)NB * HW * G];
__device__ float          g_Cq[NB * G];
__device__ float          g_part[(size_t)MBLKS * G];    // 1024 x 512
__device__ float          g_ctx[NB * G];
__device__ unsigned short g_w2h[G * G], g_w2l[G * G];
__device__ unsigned short g_w3h[G * G], g_w3l[G * G];
__device__ unsigned short g_w4h[G * G], g_w4l[G * G];

// ---------------- generic helpers ----------------
__device__ __forceinline__ void split2(float v0, float v1, unsigned &hi, unsigned &lo) {
    __nv_bfloat16 h0 = __float2bfloat16_rn(v0), h1 = __float2bfloat16_rn(v1);
    float l0f = v0 - __bfloat162float(h0), l1f = v1 - __bfloat162float(h1);
    __nv_bfloat16 l0 = __float2bfloat16_rn(l0f), l1 = __float2bfloat16_rn(l1f);
    hi = (unsigned)__bfloat16_as_ushort(h0) | ((unsigned)__bfloat16_as_ushort(h1) << 16);
    lo = (unsigned)__bfloat16_as_ushort(l0) | ((unsigned)__bfloat16_as_ushort(l1) << 16);
}
__device__ __forceinline__ float us2f(unsigned short u) {
    return __bfloat162float(__ushort_as_bfloat16(u));
}

#if TC_OK
// ---------------- tcgen05 / async PTX helpers (sm_103a only) ----------------
__device__ __forceinline__ uint32_t smem_u32(const void* p) {
    uint32_t a;
    asm("{ .reg .u64 t; cvta.to.shared.u64 t, %1; cvt.u32.u64 %0, t; }"
        : "=r"(a) : "l"(p));
    return a;
}
__device__ __forceinline__ uint32_t elect_one() {
    uint32_t p;
    asm volatile("{ .reg .pred p; elect.sync _|p, 0xFFFFFFFF; selp.b32 %0,1,0,p; }"
                 : "=r"(p));
    return p;
}
__device__ __forceinline__ void mma_bf16_ss(uint32_t d, uint64_t ad, uint64_t bd,
                                            uint32_t idesc, uint32_t en) {
    asm volatile(
        "{\n\t.reg .pred p;\n\tsetp.ne.u32 p, %4, 0;\n\t"
        "tcgen05.mma.cta_group::1.kind::f16 [%0], %1, %2, %3, {%5,%5,%5,%5}, p;\n\t}"
        :: "r"(d), "l"(ad), "l"(bd), "r"(idesc), "r"(en), "r"(0u) : "memory");
}
#define TC_ALLOC(sp, n)  asm volatile("tcgen05.alloc.cta_group::1.sync.aligned.shared::cta.b32 [%0], %1;" :: "r"(sp), "r"(n) : "memory")
#define TC_RELINQ()      asm volatile("tcgen05.relinquish_alloc_permit.cta_group::1.sync.aligned;")
#define TC_DEALLOC(t, n) asm volatile("tcgen05.dealloc.cta_group::1.sync.aligned.b32 %0, %1;" :: "r"(t), "r"(n))
#define TC_COMMIT(mb)    asm volatile("tcgen05.commit.cta_group::1.mbarrier::arrive::one.shared::cluster.b64 [%0];" :: "r"(mb) : "memory")
#define TC_FENCE_AFTER() asm volatile("tcgen05.fence::after_thread_sync;" ::: "memory")
#define TC_WAIT_LD()     asm volatile("tcgen05.wait::ld.sync.aligned;" ::: "memory")
#define FENCE_ASYNC()    asm volatile("fence.proxy.async.shared::cta;" ::: "memory")
#define MBAR_INIT(mb, c) asm volatile("mbarrier.init.shared.b64 [%0], %1;" :: "r"(mb), "r"(c) : "memory")
#define MBAR_INVAL(mb)   asm volatile("mbarrier.inval.shared.b64 [%0];" :: "r"(mb) : "memory")
#define MBAR_ARRIVE(mb)  asm volatile("mbarrier.arrive.release.cta.shared::cta.b64 _, [%0];" :: "r"(mb) : "memory")
#define MBAR_EXPECT_TX(mb, n) asm volatile("mbarrier.arrive.expect_tx.shared.b64 _, [%0], %1;" :: "r"(mb), "r"((uint32_t)(n)) : "memory")
#define TMA2D(dst, map, x, y, mb) \
    asm volatile("cp.async.bulk.tensor.2d.shared::cta.global.tile.mbarrier::complete_tx::bytes " \
                 "[%0], [%1, {%2, %3}], [%4];" \
                 :: "r"(dst), "l"(map), "r"(x), "r"(y), "r"(mb) : "memory")

__device__ __forceinline__ void mbar_wait(uint32_t mb, uint32_t parity) {
    asm volatile(
        "{\n\t.reg .pred P;\n\t"
        "WL_%=:\n\t"
        "mbarrier.try_wait.parity.acquire.cta.shared::cta.b64 P, [%0], %1, 0x989680;\n\t"
        "@P bra.uni WD_%=;\n\t"
        "bra.uni WL_%=;\n\t"
        "WD_%=:\n\t}"
        :: "r"(mb), "r"(parity) : "memory");
}
#define TC_LD_X32(r, a) \
    asm volatile("tcgen05.ld.sync.aligned.32x32b.x32.b32 " \
        "{%0,%1,%2,%3,%4,%5,%6,%7,%8,%9,%10,%11,%12,%13,%14,%15," \
        "%16,%17,%18,%19,%20,%21,%22,%23,%24,%25,%26,%27,%28,%29,%30,%31}, [%32];" \
        : "=r"((r)[0]),"=r"((r)[1]),"=r"((r)[2]),"=r"((r)[3]), \
          "=r"((r)[4]),"=r"((r)[5]),"=r"((r)[6]),"=r"((r)[7]), \
          "=r"((r)[8]),"=r"((r)[9]),"=r"((r)[10]),"=r"((r)[11]), \
          "=r"((r)[12]),"=r"((r)[13]),"=r"((r)[14]),"=r"((r)[15]), \
          "=r"((r)[16]),"=r"((r)[17]),"=r"((r)[18]),"=r"((r)[19]), \
          "=r"((r)[20]),"=r"((r)[21]),"=r"((r)[22]),"=r"((r)[23]), \
          "=r"((r)[24]),"=r"((r)[25]),"=r"((r)[26]),"=r"((r)[27]), \
          "=r"((r)[28]),"=r"((r)[29]),"=r"((r)[30]),"=r"((r)[31]) \
        : "r"(a))
#endif  // TC_OK

// ---- K1: Ai = feat_i @ W1a, Bj = feat_j @ W1b (8 positions per block) ------
__global__ void k_ab(const float* __restrict__ img, const float* __restrict__ w1) {
    int n = blockIdx.x, pg = blockIdx.y;     // 64 x 8
    int tid = threadIdx.x;                   // 512
    __shared__ float f[8][FDIM];
    if (tid < 64) {
        int c = tid;
        #pragma unroll
        for (int p8 = 0; p8 < 8; ++p8)
            f[p8][c] = img[((size_t)n * 64 + c) * 64 + pg * 8 + p8];
    } else if (tid < 72) {
        int p8 = tid - 64, p = pg * 8 + p8;
        f[p8][64] = (float)(p >> 3);
        f[p8][65] = (float)(p & 7);
    }
    __syncthreads();
    float a[8] = {0,0,0,0,0,0,0,0}, b[8] = {0,0,0,0,0,0,0,0};
    #pragma unroll 2
    for (int c = 0; c < FDIM; ++c) {
        float wa = w1[(size_t)c * G + tid];
        float wb = w1[(size_t)(c + FDIM) * G + tid];
        #pragma unroll
        for (int p8 = 0; p8 < 8; ++p8) {
            a[p8] = fmaf(f[p8][c], wa, a[p8]);
            b[p8] = fmaf(f[p8][c], wb, b[p8]);
        }
    }
    #pragma unroll
    for (int p8 = 0; p8 < 8; ++p8) {
        int row = n * 64 + pg * 8 + p8;
        g_Ai[(size_t)row * G + tid] = a[p8];
        g_Bj[(size_t)row * G + tid] = b[p8];
    }
}

// ---- K2: Cq = ques @ W1c + b1 ----------------------------------------------
__global__ void k_cq(const float* __restrict__ ques, const float* __restrict__ w1,
                     const float* __restrict__ b1) {
    int n = blockIdx.x, tid = threadIdx.x;    // 512 threads
    __shared__ float q[E];
    if (tid < E) q[tid] = ques[n * E + tid];
    __syncthreads();
    float s0 = b1[tid], s1 = 0.f;
    #pragma unroll 8
    for (int e = 0; e < E; e += 2) {
        s0 = fmaf(q[e],     w1[(size_t)(2 * FDIM + e) * G + tid], s0);
        s1 = fmaf(q[e + 1], w1[(size_t)(2 * FDIM + e + 1) * G + tid], s1);
    }
    g_Cq[n * G + tid] = s0 + s1;
}

// ---- weight prep: transpose + bf16 hi/lo split for all 3 weights -----------
__global__ void k_wprep3(const float* __restrict__ W2, const float* __restrict__ W3,
                         const float* __restrict__ W4,
                         unsigned short* __restrict__ h2, unsigned short* __restrict__ l2,
                         unsigned short* __restrict__ h3, unsigned short* __restrict__ l3,
                         unsigned short* __restrict__ h4, unsigned short* __restrict__ l4) {
    int k = blockIdx.x, n = threadIdx.x;      // 512 x 512, y selects matrix
    const float* W = (blockIdx.y == 0) ? W2 : (blockIdx.y == 1) ? W3 : W4;
    unsigned short* hi = (blockIdx.y == 0) ? h2 : (blockIdx.y == 1) ? h3 : h4;
    unsigned short* lo = (blockIdx.y == 0) ? l2 : (blockIdx.y == 1) ? l3 : l4;
    float v = W[(size_t)k * G + n];
    __nv_bfloat16 h = __float2bfloat16_rn(v);
    float hf = __bfloat162float(h);
    __nv_bfloat16 l = __float2bfloat16_rn(v - hf);
    hi[(size_t)n * G + k] = __bfloat16_as_ushort(h);
    lo[(size_t)n * G + k] = __bfloat16_as_ushort(l);
}

// ---- main tcgen05 GEMM: 256x256 tile, 3-stage TMA ring ---------------------
// MODE 0: A built by warps 2-15 from relu(Ai+Bj+Cq); B via TMA
// MODE 1: A and B via TMA; MODE 2: same + fused mean epilogue
template<int MODE>
__global__ __launch_bounds__(THREADS, 1)
void k_mma(const __grid_constant__ CUtensorMap tmAh,
           const __grid_constant__ CUtensorMap tmAl,
           const __grid_constant__ CUtensorMap tmBh,
           const __grid_constant__ CUtensorMap tmBl,
           const float* __restrict__ bias,
           unsigned short* __restrict__ oHi, unsigned short* __restrict__ oLo,
           const unsigned short* __restrict__ aHi, const unsigned short* __restrict__ aLo,
           const unsigned short* __restrict__ wHi, const unsigned short* __restrict__ wLo) {
    extern __shared__ char smem[];
#if TC_OK
    const uint32_t sbase = smem_u32(smem);
    const int tid  = threadIdx.x;
    const int wid  = tid >> 5;
    const int lane = tid & 31;
    const int mBlk = blockIdx.x;              // 0..1023
    const int nBase = blockIdx.y * BN;        // 0 or 256
    float* sBias = (float*)(smem + S_BIAS);

    const unsigned fullCnt = (MODE == 0) ? 449u : 1u;   // builders+producer / producer
    const unsigned txBytes = (MODE == 0) ? 32768u : 65536u;

    if (wid == 0) { TC_ALLOC(sbase + S_TMEM_O, 512); TC_RELINQ(); }
    if (tid == 0) {
        #pragma unroll
        for (int b = 0; b < NSTAGE; ++b) {
            MBAR_INIT(sbase + S_FULL(b), fullCnt);
            MBAR_INIT(sbase + S_FREE(b), 1);
        }
        MBAR_INIT(sbase + S_DONE, 1);
    }
    if (tid < BN) sBias[tid] = bias[nBase + tid];
    __syncthreads();
    uint32_t tmem;
    asm volatile("ld.shared.b32 %0, [%1];" : "=r"(tmem) : "r"(sbase + S_TMEM_O));

    if (wid == 1) {
        if (elect_one()) {
            // ================= TMA producer (single thread) =================
            for (int t = 0; t < TITER; ++t) {
                const int b = t % NSTAGE, kB = t * BK;
                if (t >= NSTAGE) mbar_wait(sbase + S_FREE(b), ((t - NSTAGE) / NSTAGE) & 1);
                MBAR_EXPECT_TX(sbase + S_FULL(b), txBytes);
                if (MODE != 0) {
                    TMA2D(sbase + ST_A_HI(b), &tmAh, kB, mBlk * BM, sbase + S_FULL(b));
                    TMA2D(sbase + ST_A_LO(b), &tmAl, kB, mBlk * BM, sbase + S_FULL(b));
                }
                TMA2D(sbase + ST_B_HI(b), &tmBh, kB, nBase, sbase + S_FULL(b));
                TMA2D(sbase + ST_B_LO(b), &tmBl, kB, nBase, sbase + S_FULL(b));
            }
        }
    } else if (MODE == 0 && wid >= 2) {
        // ================= A-tile builders (warps 2-15, 448 thr) ============
        const int lt = tid - 64;
        for (int t = 0; t < TITER; ++t) {
            const int b = t % NSTAGE, kB = t * BK;
            if (t >= NSTAGE) mbar_wait(sbase + S_FREE(b), ((t - NSTAGE) / NSTAGE) & 1);
            for (int idx = lt; idx < 1024; idx += 448) {
                int r = idx >> 2, u = idx & 3;     // 8 floats per unit
                size_t gr = (size_t)mBlk * BM + r;
                int n = (int)(gr >> 12), i = ((int)gr >> 6) & 63, j = (int)gr & 63;
                size_t oA = ((size_t)(n * 64 + i)) * G + kB + u * 8;
                size_t oB = ((size_t)(n * 64 + j)) * G + kB + u * 8;
                size_t oQ = (size_t)n * G + kB + u * 8;
                unsigned hw[4], lw[4];
                #pragma unroll
                for (int hh = 0; hh < 2; ++hh) {
                    float4 a4 = *(const float4*)&g_Ai[oA + hh * 4];
                    float4 b4 = *(const float4*)&g_Bj[oB + hh * 4];
                    float4 q4 = *(const float4*)&g_Cq[oQ + hh * 4];
                    float v0 = fmaxf(a4.x + b4.x + q4.x, 0.f);
                    float v1 = fmaxf(a4.y + b4.y + q4.y, 0.f);
                    float v2 = fmaxf(a4.z + b4.z + q4.z, 0.f);
                    float v3 = fmaxf(a4.w + b4.w + q4.w, 0.f);
                    split2(v0, v1, hw[hh*2],   lw[hh*2]);
                    split2(v2, v3, hw[hh*2+1], lw[hh*2+1]);
                }
                unsigned off = SWZ64((unsigned)(r * 64 + u * 16));
                *(uint4*)(smem + ST_A_HI(b) + off) = make_uint4(hw[0],hw[1],hw[2],hw[3]);
                *(uint4*)(smem + ST_A_LO(b) + off) = make_uint4(lw[0],lw[1],lw[2],lw[3]);
            }
            FENCE_ASYNC();
            MBAR_ARRIVE(sbase + S_FULL(b));
        }
    } else if (wid == 0) {
        if (elect_one()) {
            // ================= MMA issuer (single thread) ===================
            for (int t = 0; t < TITER; ++t) {
                const int b = t % NSTAGE;
                mbar_wait(sbase + S_FULL(b), (t / NSTAGE) & 1);
                uint64_t adH = MAKE_DESC64(sbase + ST_A_HI(b));
                uint64_t adL = MAKE_DESC64(sbase + ST_A_LO(b));
                uint64_t bdH = MAKE_DESC64(sbase + ST_B_HI(b));
                uint64_t bdL = MAKE_DESC64(sbase + ST_B_LO(b));
                #pragma unroll
                for (int h = 0; h < 2; ++h) {          // two M-halves
                    uint32_t d = tmem + h * 256;
                    uint64_t ah = (uint64_t)(h * 512); // 128 rows x 64B = 8192B
                    #pragma unroll
                    for (int s = 0; s < 2; ++s) {      // two K=16 chunks
                        uint64_t o = (uint64_t)(s * 2);
                        uint32_t en = ((t | s) != 0) ? 1u : 0u;
                        mma_bf16_ss(d, adH + ah + o, bdH + o, MMA_IDESC, en);
                        mma_bf16_ss(d, adH + ah + o, bdL + o, MMA_IDESC, 1u);
                        mma_bf16_ss(d, adL + ah + o, bdH + o, MMA_IDESC, 1u);
                    }
                }
                TC_COMMIT(sbase + S_FREE(b));
            }
            TC_COMMIT(sbase + S_DONE);
        }
    }

    // all threads wait for the final MMA
    mbar_wait(sbase + S_DONE, 0);
    TC_FENCE_AFTER();

    // ---- epilogue: 8 warps (2 warpgroups) read the 2 D halves --------------
    float* sPart = (float*)(smem + ST_A_HI(0));   // [8][256] for MODE 2
    if (wid < 8) {
        const int half = wid >> 2;
        const int sub  = wid & 3;
        size_t grow = (size_t)mBlk * BM + half * 128 + sub * 32 + lane;
        #pragma unroll 1
        for (int c = 0; c < 8; ++c) {
            uint32_t r[32];
            TC_LD_X32(r, tmem + half * 256 + c * 32);
            TC_WAIT_LD();
            int cc = c * 32;
            if (MODE < 2) {
                #pragma unroll
                for (int q = 0; q < 4; ++q) {
                    unsigned hw[4], lw[4];
                    #pragma unroll
                    for (int e = 0; e < 4; ++e) {
                        float v0 = fmaxf(__uint_as_float(r[q*8+e*2])   + sBias[cc+q*8+e*2],   0.f);
                        float v1 = fmaxf(__uint_as_float(r[q*8+e*2+1]) + sBias[cc+q*8+e*2+1], 0.f);
                        split2(v0, v1, hw[e], lw[e]);
                    }
                    size_t go = grow * G + nBase + cc + q * 8;
                    *(uint4*)&oHi[go] = make_uint4(hw[0], hw[1], hw[2], hw[3]);
                    *(uint4*)&oLo[go] = make_uint4(lw[0], lw[1], lw[2], lw[3]);
                }
            } else {
                #pragma unroll
                for (int j = 0; j < 32; ++j) {
                    float v = fmaxf(__uint_as_float(r[j]) + sBias[cc + j], 0.f);
                    #pragma unroll
                    for (int o = 16; o > 0; o >>= 1)
                        v += __shfl_xor_sync(0xFFFFFFFFu, v, o);
                    if (lane == 0) sPart[wid * 256 + cc + j] = v;
                }
            }
        }
    }
    __syncthreads();
    if (MODE == 2 && tid < BN) {
        float s = 0.f;
        #pragma unroll
        for (int w = 0; w < 8; ++w) s += sPart[w * 256 + tid];
        g_part[(size_t)mBlk * G + nBase + tid] = s;
    }
    __syncthreads();
    if (tid == 0) {
        #pragma unroll
        for (int b = 0; b < NSTAGE; ++b) {
            MBAR_INVAL(sbase + S_FULL(b)); MBAR_INVAL(sbase + S_FREE(b));
        }
        MBAR_INVAL(sbase + S_DONE);
    }
    __syncthreads();
    if (wid == 0) TC_DEALLOC(tmem, 512);
#else
    // -------- scalar fallback (non-sm_103a compile passes only) --------
    const int tid  = threadIdx.x;
    const int mBlk = blockIdx.x;
    const int nBase = blockIdx.y * BN;
    if (tid >= BN) return;
    const int col = nBase + tid;
    float colsum = 0.f;
    for (int r = 0; r < BM; ++r) {
        size_t gr = (size_t)mBlk * BM + r;
        float acc = bias[col];
        int n = (int)(gr >> 12), i = ((int)gr >> 6) & 63, j = (int)gr & 63;
        for (int k = 0; k < G; ++k) {
            float a;
            if (MODE == 0) {
                float raw = fmaxf(g_Ai[((size_t)(n * 64 + i)) * G + k]
                                + g_Bj[((size_t)(n * 64 + j)) * G + k]
                                + g_Cq[(size_t)n * G + k], 0.f);
                unsigned hh, ll;
                split2(raw, 0.f, hh, ll);
                a = us2f((unsigned short)(hh & 0xFFFFu)) + us2f((unsigned short)(ll & 0xFFFFu));
            } else {
                a = us2f(aHi[gr * G + k]) + us2f(aLo[gr * G + k]);
            }
            float w = us2f(wHi[(size_t)col * G + k]) + us2f(wLo[(size_t)col * G + k]);
            acc = fmaf(a, w, acc);
        }
        float v = fmaxf(acc, 0.f);
        if (MODE < 2) {
            unsigned hh, ll;
            split2(v, 0.f, hh, ll);
            oHi[gr * G + col] = (unsigned short)(hh & 0xFFFFu);
            oLo[gr * G + col] = (unsigned short)(ll & 0xFFFFu);
        } else colsum += v;
    }
    if (MODE == 2) g_part[(size_t)mBlk * G + col] = colsum;
#endif
}

// ---- final mean over 4096 pairs (16 partial blocks per image) --------------
__global__ void k_reduce2() {
    int n = blockIdx.x, k = threadIdx.x;   // 64 x 512
    float s = 0.f;
    #pragma unroll
    for (int b = 0; b < 16; ++b)
        s += g_part[(size_t)(n * 16 + b) * G + k];
    g_ctx[n * G + k] = s * (1.0f / 4096.0f);
}

// ---- f-MLP + log_softmax ---------------------------------------------------
__global__ void k_fmlp(const float* __restrict__ fw1, const float* __restrict__ fb1,
                       const float* __restrict__ fw2, const float* __restrict__ fb2,
                       const float* __restrict__ fw3, const float* __restrict__ fb3,
                       float* __restrict__ out) {
    int n = blockIdx.x, tid = threadIdx.x;   // 512 threads
    __shared__ float x[G], y[G];
    __shared__ float sc[2];
    x[tid] = g_ctx[n * G + tid];
    __syncthreads();
    float s0 = fb1[tid], s1 = 0.f;
    #pragma unroll 8
    for (int c = 0; c < G; c += 2) {
        s0 = fmaf(x[c],     fw1[(size_t)c * G + tid], s0);
        s1 = fmaf(x[c + 1], fw1[(size_t)(c + 1) * G + tid], s1);
    }
    y[tid] = fmaxf(s0 + s1, 0.f);
    __syncthreads();
    s0 = fb2[tid]; s1 = 0.f;
    #pragma unroll 8
    for (int c = 0; c < G; c += 2) {
        s0 = fmaf(y[c],     fw2[(size_t)c * G + tid], s0);
        s1 = fmaf(y[c + 1], fw2[(size_t)(c + 1) * G + tid], s1);
    }
    x[tid] = fmaxf(s0 + s1, 0.f);
    __syncthreads();
    if (tid < 2) {
        float t = fb3[tid];
        for (int c = 0; c < G; ++c) t = fmaf(x[c], fw3[c * 2 + tid], t);
        sc[tid] = t;
    }
    __syncthreads();
    if (tid == 0) {
        float m = fmaxf(sc[0], sc[1]);
        float lse = m + logf(expf(sc[0] - m) + expf(sc[1] - m));
        out[n * 2 + 0] = sc[0] - lse;
        out[n * 2 + 1] = sc[1] - lse;
    }
}

// ---------------- host: tensormap building ----------------
typedef CUresult (*EncodeFn)(CUtensorMap*, CUtensorMapDataType, cuuint32_t, void*,
                             const cuuint64_t*, const cuuint64_t*, const cuuint32_t*,
                             const cuuint32_t*, CUtensorMapInterleave, CUtensorMapSwizzle,
                             CUtensorMapL2promotion, CUtensorMapFloatOOBfill);

static EncodeFn get_encoder() {
    void* fn = nullptr;
    cudaDriverEntryPointQueryResult st;
    cudaGetDriverEntryPoint("cuTensorMapEncodeTiled", &fn, cudaEnableDefault, &st);
    return (EncodeFn)fn;
}
static void build_map(EncodeFn enc, CUtensorMap* m, void* base,
                      unsigned long long rows, unsigned boxRows) {
    cuuint64_t dims[2]    = {(cuuint64_t)G, (cuuint64_t)rows};
    cuuint64_t strides[1] = {(cuuint64_t)G * 2};   // bf16 bytes
    cuuint32_t box[2]     = {(cuuint32_t)BK, (cuuint32_t)boxRows};
    cuuint32_t es[2]      = {1, 1};
    enc(m, CU_TENSOR_MAP_DATA_TYPE_BFLOAT16, 2, base, dims, strides, box, es,
        CU_TENSOR_MAP_INTERLEAVE_NONE, CU_TENSOR_MAP_SWIZZLE_64B,
        CU_TENSOR_MAP_L2_PROMOTION_L2_128B, CU_TENSOR_MAP_FLOAT_OOB_FILL_NONE);
}

// ----------------------------------------------------------------------------
extern "C" void kernel_launch(void* const* d_in, const int* in_sizes, int n_in,
                              void* d_out, int out_size) {
    const float* img  = (const float*)d_in[0];
    const float* ques = (const float*)d_in[1];
    const float* g_w1 = (const float*)d_in[2];
    const float* g_b1 = (const float*)d_in[3];
    const float* g_w2 = (const float*)d_in[4];
    const float* g_b2 = (const float*)d_in[5];
    const float* g_w3 = (const float*)d_in[6];
    const float* g_b3 = (const float*)d_in[7];
    const float* g_w4 = (const float*)d_in[8];
    const float* g_b4 = (const float*)d_in[9];
    const float* f_w1 = (const float*)d_in[10];
    const float* f_b1 = (const float*)d_in[11];
    const float* f_w2 = (const float*)d_in[12];
    const float* f_b2 = (const float*)d_in[13];
    const float* f_w3 = (const float*)d_in[14];
    const float* f_b3 = (const float*)d_in[15];
    float* out = (float*)d_out;

    cudaFuncSetAttribute(k_mma<0>, cudaFuncAttributeMaxDynamicSharedMemorySize, SMEM_SZ);
    cudaFuncSetAttribute(k_mma<1>, cudaFuncAttributeMaxDynamicSharedMemorySize, SMEM_SZ);
    cudaFuncSetAttribute(k_mma<2>, cudaFuncAttributeMaxDynamicSharedMemorySize, SMEM_SZ);

    unsigned short *w2h, *w2l, *w3h, *w3l, *w4h, *w4l, *h2h, *h2l, *h3h, *h3l;
    cudaGetSymbolAddress((void**)&w2h, g_w2h); cudaGetSymbolAddress((void**)&w2l, g_w2l);
    cudaGetSymbolAddress((void**)&w3h, g_w3h); cudaGetSymbolAddress((void**)&w3l, g_w3l);
    cudaGetSymbolAddress((void**)&w4h, g_w4h); cudaGetSymbolAddress((void**)&w4l, g_w4l);
    cudaGetSymbolAddress((void**)&h2h, g_h2h); cudaGetSymbolAddress((void**)&h2l, g_h2l);
    cudaGetSymbolAddress((void**)&h3h, g_h3h); cudaGetSymbolAddress((void**)&h3l, g_h3l);

    EncodeFn enc = get_encoder();
    CUtensorMap mW2h, mW2l, mW3h, mW3l, mW4h, mW4l, mA2h, mA2l, mA3h, mA3l;
    build_map(enc, &mW2h, w2h, G, BN);       build_map(enc, &mW2l, w2l, G, BN);
    build_map(enc, &mW3h, w3h, G, BN);       build_map(enc, &mW3l, w3l, G, BN);
    build_map(enc, &mW4h, w4h, G, BN);       build_map(enc, &mW4l, w4l, G, BN);
    build_map(enc, &mA2h, h2h, MROWS, BM);   build_map(enc, &mA2l, h2l, MROWS, BM);
    build_map(enc, &mA3h, h3h, MROWS, BM);   build_map(enc, &mA3l, h3l, MROWS, BM);

    k_wprep3<<<dim3(G, 3), G>>>(g_w2, g_w3, g_w4, w2h, w2l, w3h, w3l, w4h, w4l);
    k_ab<<<dim3(NB, 8), 512>>>(img, g_w1);
    k_cq<<<NB, 512>>>(ques, g_w1, g_b1);

    dim3 gg(MBLKS, G / BN);   // 1024 x 2
    k_mma<0><<<gg, THREADS, SMEM_SZ>>>(mW2h, mW2l, mW2h, mW2l, g_b2, h2h, h2l,
                                       nullptr, nullptr, w2h, w2l);
    k_mma<1><<<gg, THREADS, SMEM_SZ>>>(mA2h, mA2l, mW3h, mW3l, g_b3, h3h, h3l,
                                       h2h, h2l, w3h, w3l);
    k_mma<2><<<gg, THREADS, SMEM_SZ>>>(mA3h, mA3l, mW4h, mW4l, g_b4, nullptr, nullptr,
                                       h3h, h3l, w4h, w4l);

    k_reduce2<<<NB, 512>>>();
    k_fmlp<<<NB, 512>>>(f_w1, f_b1, f_w2, f_b2, f_w3, f_b3, out);
}

// round 12
// speedup vs baseline: 1.3766x; 1.0075x over previous
#include <cuda_runtime.h>
#include <cuda.h>
#include <cuda_bf16.h>
#include <math.h>
#include <stdint.h>

// ----------------------------------------------------------------------------
// RelNet forward, tcgen05 sm_103a, bf16 hi/lo split GEMMs.
// BM=256 x BN=256 tiles, TMEM 512, 3-stage TMA ring, ALU-only trunc splits.
// ----------------------------------------------------------------------------

#if defined(__CUDA_ARCH__) && (defined(__CUDA_ARCH_FEAT_SM103_ALL) || \
    defined(__CUDA_ARCH_FEAT_SM100_ALL) || defined(__CUDA_ARCH_FEAT_SM101_ALL))
#define TC_OK 1
#else
#define TC_OK 0
#endif

#define NB   64
#define HW   64
#define FDIM 66
#define G    512
#define E    256
#define MROWS (NB * HW * HW)   // 262144

#define BM 256
#define BN 256
#define BK 32
#define TITER (G / BK)         // 16
#define NSTAGE 3
#define THREADS 512
#define MBLKS (MROWS / BM)     // 1024

// SMEM: 4KB ctrl + 3 stages x 64KB
#define S_TMEM_O  0
#define S_FULL(b) (8 + (b) * 8)
#define S_FREE(b) (32 + (b) * 8)
#define S_DONE    56
#define S_BIAS    64
#define STAGE_SZ  65536
#define ST_A_HI(b) (4096 + (b) * STAGE_SZ)
#define ST_A_LO(b) (ST_A_HI(b) + 16384)
#define ST_B_HI(b) (ST_A_HI(b) + 32768)
#define ST_B_LO(b) (ST_A_HI(b) + 49152)
#define SMEM_SZ    (4096 + NSTAGE * STAGE_SZ)   // 200704 -> 1 CTA/SM

// idesc: kind::f16, dtype=F32, atype=BF16, btype=BF16, N=256, M=128
#define MMA_IDESC ((1u<<4)|(1u<<7)|(1u<<10)|(32u<<17)|(8u<<24))

// SW64 K-major descriptor (layout=4, version=1, SBO=32, LBO=1); 64B rows
#define SMEM_DESC_BASE_SW64 \
    ((uint64_t(4)<<61)|(uint64_t(1)<<46)|(uint64_t(32)<<32)|(uint64_t(1)<<16))
#define MAKE_DESC64(a) (SMEM_DESC_BASE_SW64 | ((uint64_t)((a) >> 4) & 0x3FFF))
#define SWZ64(o) ((o) ^ (((o) >> 3) & 0x30))

// ---------------- device scratch (separate hi/lo planes) ----------------
__device__ unsigned short g_h2h[(size_t)MROWS * G], g_h2l[(size_t)MROWS * G];
__device__ unsigned short g_h3h[(size_t)MROWS * G], g_h3l[(size_t)MROWS * G];
__device__ float          g_Ai[(size_t)NB * HW * G];
__device__ float          g_Bj[(size_t)NB * HW * G];
__device__ float          g_Cq[NB * G];
__device__ float          g_part[(size_t)MBLKS * G];    // 1024 x 512
__device__ float          g_ctx[NB * G];
__device__ unsigned short g_w2h[G * G], g_w2l[G * G];
__device__ unsigned short g_w3h[G * G], g_w3l[G * G];
__device__ unsigned short g_w4h[G * G], g_w4l[G * G];

// ---------------- generic helpers ----------------
// Truncation-based hi/lo split: ALU-only (PRMT/LOP3/FSUB), no cvt instructions.
// hi = top 16 bits of v (bf16 by truncation); lo = bf16-trunc of (v - hi_f32).
// v - hi is exact in fp32 (<=16 significant bits); residual <= 2^-15 |v|.
__device__ __forceinline__ void split2t(float v0, float v1, unsigned &hi, unsigned &lo) {
    unsigned u0 = __float_as_uint(v0), u1 = __float_as_uint(v1);
    hi = __byte_perm(u0, u1, 0x7632);
    float l0 = v0 - __uint_as_float(u0 & 0xFFFF0000u);
    float l1 = v1 - __uint_as_float(u1 & 0xFFFF0000u);
    lo = __byte_perm(__float_as_uint(l0), __float_as_uint(l1), 0x7632);
}
__device__ __forceinline__ float us2f(unsigned short u) {
    return __bfloat162float(__ushort_as_bfloat16(u));
}

#if TC_OK
// ---------------- tcgen05 / async PTX helpers (sm_103a only) ----------------
__device__ __forceinline__ uint32_t smem_u32(const void* p) {
    uint32_t a;
    asm("{ .reg .u64 t; cvta.to.shared.u64 t, %1; cvt.u32.u64 %0, t; }"
        : "=r"(a) : "l"(p));
    return a;
}
__device__ __forceinline__ uint32_t elect_one() {
    uint32_t p;
    asm volatile("{ .reg .pred p; elect.sync _|p, 0xFFFFFFFF; selp.b32 %0,1,0,p; }"
                 : "=r"(p));
    return p;
}
__device__ __forceinline__ void mma_bf16_ss(uint32_t d, uint64_t ad, uint64_t bd,
                                            uint32_t idesc, uint32_t en) {
    asm volatile(
        "{\n\t.reg .pred p;\n\tsetp.ne.u32 p, %4, 0;\n\t"
        "tcgen05.mma.cta_group::1.kind::f16 [%0], %1, %2, %3, {%5,%5,%5,%5}, p;\n\t}"
        :: "r"(d), "l"(ad), "l"(bd), "r"(idesc), "r"(en), "r"(0u) : "memory");
}
#define TC_ALLOC(sp, n)  asm volatile("tcgen05.alloc.cta_group::1.sync.aligned.shared::cta.b32 [%0], %1;" :: "r"(sp), "r"(n) : "memory")
#define TC_RELINQ()      asm volatile("tcgen05.relinquish_alloc_permit.cta_group::1.sync.aligned;")
#define TC_DEALLOC(t, n) asm volatile("tcgen05.dealloc.cta_group::1.sync.aligned.b32 %0, %1;" :: "r"(t), "r"(n))
#define TC_COMMIT(mb)    asm volatile("tcgen05.commit.cta_group::1.mbarrier::arrive::one.shared::cluster.b64 [%0];" :: "r"(mb) : "memory")
#define TC_FENCE_AFTER() asm volatile("tcgen05.fence::after_thread_sync;" ::: "memory")
#define TC_WAIT_LD()     asm volatile("tcgen05.wait::ld.sync.aligned;" ::: "memory")
#define FENCE_ASYNC()    asm volatile("fence.proxy.async.shared::cta;" ::: "memory")
#define MBAR_INIT(mb, c) asm volatile("mbarrier.init.shared.b64 [%0], %1;" :: "r"(mb), "r"(c) : "memory")
#define MBAR_INVAL(mb)   asm volatile("mbarrier.inval.shared.b64 [%0];" :: "r"(mb) : "memory")
#define MBAR_ARRIVE(mb)  asm volatile("mbarrier.arrive.release.cta.shared::cta.b64 _, [%0];" :: "r"(mb) : "memory")
#define MBAR_EXPECT_TX(mb, n) asm volatile("mbarrier.arrive.expect_tx.shared.b64 _, [%0], %1;" :: "r"(mb), "r"((uint32_t)(n)) : "memory")
#define TMA2D(dst, map, x, y, mb) \
    asm volatile("cp.async.bulk.tensor.2d.shared::cta.global.tile.mbarrier::complete_tx::bytes " \
                 "[%0], [%1, {%2, %3}], [%4];" \
                 :: "r"(dst), "l"(map), "r"(x), "r"(y), "r"(mb) : "memory")

__device__ __forceinline__ void mbar_wait(uint32_t mb, uint32_t parity) {
    asm volatile(
        "{\n\t.reg .pred P;\n\t"
        "WL_%=:\n\t"
        "mbarrier.try_wait.parity.acquire.cta.shared::cta.b64 P, [%0], %1, 0x989680;\n\t"
        "@P bra.uni WD_%=;\n\t"
        "bra.uni WL_%=;\n\t"
        "WD_%=:\n\t}"
        :: "r"(mb), "r"(parity) : "memory");
}
#define TC_LD_X32(r, a) \
    asm volatile("tcgen05.ld.sync.aligned.32x32b.x32.b32 " \
        "{%0,%1,%2,%3,%4,%5,%6,%7,%8,%9,%10,%11,%12,%13,%14,%15," \
        "%16,%17,%18,%19,%20,%21,%22,%23,%24,%25,%26,%27,%28,%29,%30,%31}, [%32];" \
        : "=r"((r)[0]),"=r"((r)[1]),"=r"((r)[2]),"=r"((r)[3]), \
          "=r"((r)[4]),"=r"((r)[5]),"=r"((r)[6]),"=r"((r)[7]), \
          "=r"((r)[8]),"=r"((r)[9]),"=r"((r)[10]),"=r"((r)[11]), \
          "=r"((r)[12]),"=r"((r)[13]),"=r"((r)[14]),"=r"((r)[15]), \
          "=r"((r)[16]),"=r"((r)[17]),"=r"((r)[18]),"=r"((r)[19]), \
          "=r"((r)[20]),"=r"((r)[21]),"=r"((r)[22]),"=r"((r)[23]), \
          "=r"((r)[24]),"=r"((r)[25]),"=r"((r)[26]),"=r"((r)[27]), \
          "=r"((r)[28]),"=r"((r)[29]),"=r"((r)[30]),"=r"((r)[31]) \
        : "r"(a))
#endif  // TC_OK

// ---- K1: Ai = feat_i @ W1a, Bj = feat_j @ W1b (8 positions per block) ------
__global__ void k_ab(const float* __restrict__ img, const float* __restrict__ w1) {
    int n = blockIdx.x, pg = blockIdx.y;     // 64 x 8
    int tid = threadIdx.x;                   // 512
    __shared__ float f[8][FDIM];
    if (tid < 64) {
        int c = tid;
        #pragma unroll
        for (int p8 = 0; p8 < 8; ++p8)
            f[p8][c] = img[((size_t)n * 64 + c) * 64 + pg * 8 + p8];
    } else if (tid < 72) {
        int p8 = tid - 64, p = pg * 8 + p8;
        f[p8][64] = (float)(p >> 3);
        f[p8][65] = (float)(p & 7);
    }
    __syncthreads();
    float a[8] = {0,0,0,0,0,0,0,0}, b[8] = {0,0,0,0,0,0,0,0};
    #pragma unroll 2
    for (int c = 0; c < FDIM; ++c) {
        float wa = w1[(size_t)c * G + tid];
        float wb = w1[(size_t)(c + FDIM) * G + tid];
        #pragma unroll
        for (int p8 = 0; p8 < 8; ++p8) {
            a[p8] = fmaf(f[p8][c], wa, a[p8]);
            b[p8] = fmaf(f[p8][c], wb, b[p8]);
        }
    }
    #pragma unroll
    for (int p8 = 0; p8 < 8; ++p8) {
        int row = n * 64 + pg * 8 + p8;
        g_Ai[(size_t)row * G + tid] = a[p8];
        g_Bj[(size_t)row * G + tid] = b[p8];
    }
}

// ---- K2: Cq = ques @ W1c + b1 ----------------------------------------------
__global__ void k_cq(const float* __restrict__ ques, const float* __restrict__ w1,
                     const float* __restrict__ b1) {
    int n = blockIdx.x, tid = threadIdx.x;    // 512 threads
    __shared__ float q[E];
    if (tid < E) q[tid] = ques[n * E + tid];
    __syncthreads();
    float s0 = b1[tid], s1 = 0.f;
    #pragma unroll 8
    for (int e = 0; e < E; e += 2) {
        s0 = fmaf(q[e],     w1[(size_t)(2 * FDIM + e) * G + tid], s0);
        s1 = fmaf(q[e + 1], w1[(size_t)(2 * FDIM + e + 1) * G + tid], s1);
    }
    g_Cq[n * G + tid] = s0 + s1;
}

// ---- weight prep: transpose + bf16 hi/lo split (RN, done once) -------------
__global__ void k_wprep3(const float* __restrict__ W2, const float* __restrict__ W3,
                         const float* __restrict__ W4,
                         unsigned short* __restrict__ h2, unsigned short* __restrict__ l2,
                         unsigned short* __restrict__ h3, unsigned short* __restrict__ l3,
                         unsigned short* __restrict__ h4, unsigned short* __restrict__ l4) {
    int k = blockIdx.x, n = threadIdx.x;      // 512 x 512, y selects matrix
    const float* W = (blockIdx.y == 0) ? W2 : (blockIdx.y == 1) ? W3 : W4;
    unsigned short* hi = (blockIdx.y == 0) ? h2 : (blockIdx.y == 1) ? h3 : h4;
    unsigned short* lo = (blockIdx.y == 0) ? l2 : (blockIdx.y == 1) ? l3 : l4;
    float v = W[(size_t)k * G + n];
    __nv_bfloat16 h = __float2bfloat16_rn(v);
    float hf = __bfloat162float(h);
    __nv_bfloat16 l = __float2bfloat16_rn(v - hf);
    hi[(size_t)n * G + k] = __bfloat16_as_ushort(h);
    lo[(size_t)n * G + k] = __bfloat16_as_ushort(l);
}

// ---- main tcgen05 GEMM: 256x256 tile, 3-stage TMA ring ---------------------
// MODE 0: A built by warps 2-15 from relu(Ai+Bj+Cq); B via TMA
// MODE 1: A and B via TMA; MODE 2: same + fused mean epilogue
template<int MODE>
__global__ __launch_bounds__(THREADS, 1)
void k_mma(const __grid_constant__ CUtensorMap tmAh,
           const __grid_constant__ CUtensorMap tmAl,
           const __grid_constant__ CUtensorMap tmBh,
           const __grid_constant__ CUtensorMap tmBl,
           const float* __restrict__ bias,
           unsigned short* __restrict__ oHi, unsigned short* __restrict__ oLo,
           const unsigned short* __restrict__ aHi, const unsigned short* __restrict__ aLo,
           const unsigned short* __restrict__ wHi, const unsigned short* __restrict__ wLo) {
    extern __shared__ char smem[];
#if TC_OK
    const uint32_t sbase = smem_u32(smem);
    const int tid  = threadIdx.x;
    const int wid  = tid >> 5;
    const int lane = tid & 31;
    const int mBlk = blockIdx.x;              // 0..1023
    const int nBase = blockIdx.y * BN;        // 0 or 256
    float* sBias = (float*)(smem + S_BIAS);

    const unsigned fullCnt = (MODE == 0) ? 15u : 1u;    // 14 builder warps + producer
    const unsigned txBytes = (MODE == 0) ? 32768u : 65536u;

    if (wid == 0) { TC_ALLOC(sbase + S_TMEM_O, 512); TC_RELINQ(); }
    if (tid == 0) {
        #pragma unroll
        for (int b = 0; b < NSTAGE; ++b) {
            MBAR_INIT(sbase + S_FULL(b), fullCnt);
            MBAR_INIT(sbase + S_FREE(b), 1);
        }
        MBAR_INIT(sbase + S_DONE, 1);
    }
    if (tid < BN) sBias[tid] = bias[nBase + tid];
    __syncthreads();
    uint32_t tmem;
    asm volatile("ld.shared.b32 %0, [%1];" : "=r"(tmem) : "r"(sbase + S_TMEM_O));

    if (wid == 1) {
        if (elect_one()) {
            // ================= TMA producer (single thread) =================
            for (int t = 0; t < TITER; ++t) {
                const int b = t % NSTAGE, kB = t * BK;
                if (t >= NSTAGE) mbar_wait(sbase + S_FREE(b), ((t - NSTAGE) / NSTAGE) & 1);
                MBAR_EXPECT_TX(sbase + S_FULL(b), txBytes);
                if (MODE != 0) {
                    TMA2D(sbase + ST_A_HI(b), &tmAh, kB, mBlk * BM, sbase + S_FULL(b));
                    TMA2D(sbase + ST_A_LO(b), &tmAl, kB, mBlk * BM, sbase + S_FULL(b));
                }
                TMA2D(sbase + ST_B_HI(b), &tmBh, kB, nBase, sbase + S_FULL(b));
                TMA2D(sbase + ST_B_LO(b), &tmBl, kB, nBase, sbase + S_FULL(b));
            }
        }
    } else if (MODE == 0 && wid >= 2) {
        // ================= A-tile builders (warps 2-15, 448 thr) ============
        const int lt = tid - 64;
        for (int t = 0; t < TITER; ++t) {
            const int b = t % NSTAGE, kB = t * BK;
            if (t >= NSTAGE) mbar_wait(sbase + S_FREE(b), ((t - NSTAGE) / NSTAGE) & 1);
            for (int idx = lt; idx < 1024; idx += 448) {
                int r = idx >> 2, u = idx & 3;     // 8 floats per unit
                size_t gr = (size_t)mBlk * BM + r;
                int n = (int)(gr >> 12), i = ((int)gr >> 6) & 63, j = (int)gr & 63;
                size_t oA = ((size_t)(n * 64 + i)) * G + kB + u * 8;
                size_t oB = ((size_t)(n * 64 + j)) * G + kB + u * 8;
                size_t oQ = (size_t)n * G + kB + u * 8;
                unsigned hw[4], lw[4];
                #pragma unroll
                for (int hh = 0; hh < 2; ++hh) {
                    float4 a4 = *(const float4*)&g_Ai[oA + hh * 4];
                    float4 b4 = *(const float4*)&g_Bj[oB + hh * 4];
                    float4 q4 = *(const float4*)&g_Cq[oQ + hh * 4];
                    float v0 = fmaxf(a4.x + b4.x + q4.x, 0.f);
                    float v1 = fmaxf(a4.y + b4.y + q4.y, 0.f);
                    float v2 = fmaxf(a4.z + b4.z + q4.z, 0.f);
                    float v3 = fmaxf(a4.w + b4.w + q4.w, 0.f);
                    split2t(v0, v1, hw[hh*2],   lw[hh*2]);
                    split2t(v2, v3, hw[hh*2+1], lw[hh*2+1]);
                }
                unsigned off = SWZ64((unsigned)(r * 64 + u * 16));
                *(uint4*)(smem + ST_A_HI(b) + off) = make_uint4(hw[0],hw[1],hw[2],hw[3]);
                *(uint4*)(smem + ST_A_LO(b) + off) = make_uint4(lw[0],lw[1],lw[2],lw[3]);
            }
            FENCE_ASYNC();
            __syncwarp();
            if (elect_one()) MBAR_ARRIVE(sbase + S_FULL(b));
        }
    } else if (wid == 0) {
        if (elect_one()) {
            // ================= MMA issuer (single thread) ===================
            for (int t = 0; t < TITER; ++t) {
                const int b = t % NSTAGE;
                mbar_wait(sbase + S_FULL(b), (t / NSTAGE) & 1);
                uint64_t adH = MAKE_DESC64(sbase + ST_A_HI(b));
                uint64_t adL = MAKE_DESC64(sbase + ST_A_LO(b));
                uint64_t bdH = MAKE_DESC64(sbase + ST_B_HI(b));
                uint64_t bdL = MAKE_DESC64(sbase + ST_B_LO(b));
                #pragma unroll
                for (int h = 0; h < 2; ++h) {          // two M-halves
                    uint32_t d = tmem + h * 256;
                    uint64_t ah = (uint64_t)(h * 512); // 128 rows x 64B / 16
                    #pragma unroll
                    for (int s = 0; s < 2; ++s) {      // two K=16 chunks
                        uint64_t o = (uint64_t)(s * 2);
                        uint32_t en = ((t | s) != 0) ? 1u : 0u;
                        mma_bf16_ss(d, adH + ah + o, bdH + o, MMA_IDESC, en);
                        mma_bf16_ss(d, adH + ah + o, bdL + o, MMA_IDESC, 1u);
                        mma_bf16_ss(d, adL + ah + o, bdH + o, MMA_IDESC, 1u);
                    }
                }
                TC_COMMIT(sbase + S_FREE(b));
            }
            TC_COMMIT(sbase + S_DONE);
        }
    }

    // all threads wait for the final MMA
    mbar_wait(sbase + S_DONE, 0);
    TC_FENCE_AFTER();

    // ---- epilogue: 8 warps (2 warpgroups) read the 2 D halves --------------
    float* sPart = (float*)(smem + ST_A_HI(0));   // [8][256] for MODE 2
    if (wid < 8) {
        const int half = wid >> 2;
        const int sub  = wid & 3;
        size_t grow = (size_t)mBlk * BM + half * 128 + sub * 32 + lane;
        #pragma unroll 1
        for (int cp = 0; cp < 4; ++cp) {
            uint32_t rA[32], rB[32];
            TC_LD_X32(rA, tmem + half * 256 + cp * 64);
            TC_LD_X32(rB, tmem + half * 256 + cp * 64 + 32);
            TC_WAIT_LD();
            #pragma unroll
            for (int hh = 0; hh < 2; ++hh) {
                uint32_t* r = hh ? rB : rA;
                int cc = cp * 64 + hh * 32;
                if (MODE < 2) {
                    #pragma unroll
                    for (int q = 0; q < 4; ++q) {
                        unsigned hw[4], lw[4];
                        #pragma unroll
                        for (int e = 0; e < 4; ++e) {
                            float v0 = fmaxf(__uint_as_float(r[q*8+e*2])   + sBias[cc+q*8+e*2],   0.f);
                            float v1 = fmaxf(__uint_as_float(r[q*8+e*2+1]) + sBias[cc+q*8+e*2+1], 0.f);
                            split2t(v0, v1, hw[e], lw[e]);
                        }
                        size_t go = grow * G + nBase + cc + q * 8;
                        *(uint4*)&oHi[go] = make_uint4(hw[0], hw[1], hw[2], hw[3]);
                        *(uint4*)&oLo[go] = make_uint4(lw[0], lw[1], lw[2], lw[3]);
                    }
                } else {
                    #pragma unroll
                    for (int j = 0; j < 32; ++j) {
                        float v = fmaxf(__uint_as_float(r[j]) + sBias[cc + j], 0.f);
                        #pragma unroll
                        for (int o = 16; o > 0; o >>= 1)
                            v += __shfl_xor_sync(0xFFFFFFFFu, v, o);
                        if (lane == 0) sPart[wid * 256 + cc + j] = v;
                    }
                }
            }
        }
    }
    __syncthreads();
    if (MODE == 2 && tid < BN) {
        float s = 0.f;
        #pragma unroll
        for (int w = 0; w < 8; ++w) s += sPart[w * 256 + tid];
        g_part[(size_t)mBlk * G + nBase + tid] = s;
    }
    __syncthreads();
    if (tid == 0) {
        #pragma unroll
        for (int b = 0; b < NSTAGE; ++b) {
            MBAR_INVAL(sbase + S_FULL(b)); MBAR_INVAL(sbase + S_FREE(b));
        }
        MBAR_INVAL(sbase + S_DONE);
    }
    __syncthreads();
    if (wid == 0) TC_DEALLOC(tmem, 512);
#else
    // -------- scalar fallback (non-sm_103a compile passes only) --------
    const int tid  = threadIdx.x;
    const int mBlk = blockIdx.x;
    const int nBase = blockIdx.y * BN;
    if (tid >= BN) return;
    const int col = nBase + tid;
    float colsum = 0.f;
    for (int r = 0; r < BM; ++r) {
        size_t gr = (size_t)mBlk * BM + r;
        float acc = bias[col];
        int n = (int)(gr >> 12), i = ((int)gr >> 6) & 63, j = (int)gr & 63;
        for (int k = 0; k < G; ++k) {
            float a;
            if (MODE == 0) {
                float raw = fmaxf(g_Ai[((size_t)(n * 64 + i)) * G + k]
                                + g_Bj[((size_t)(n * 64 + j)) * G + k]
                                + g_Cq[(size_t)n * G + k], 0.f);
                unsigned hh, ll;
                split2t(raw, 0.f, hh, ll);
                a = us2f((unsigned short)(hh & 0xFFFFu)) + us2f((unsigned short)(ll & 0xFFFFu));
            } else {
                a = us2f(aHi[gr * G + k]) + us2f(aLo[gr * G + k]);
            }
            float w = us2f(wHi[(size_t)col * G + k]) + us2f(wLo[(size_t)col * G + k]);
            acc = fmaf(a, w, acc);
        }
        float v = fmaxf(acc, 0.f);
        if (MODE < 2) {
            unsigned hh, ll;
            split2t(v, 0.f, hh, ll);
            oHi[gr * G + col] = (unsigned short)(hh & 0xFFFFu);
            oLo[gr * G + col] = (unsigned short)(ll & 0xFFFFu);
        } else colsum += v;
    }
    if (MODE == 2) g_part[(size_t)mBlk * G + col] = colsum;
#endif
}

// ---- final mean over 4096 pairs (16 partial blocks per image) --------------
__global__ void k_reduce2() {
    int n = blockIdx.x, k = threadIdx.x;   // 64 x 512
    float s = 0.f;
    #pragma unroll
    for (int b = 0; b < 16; ++b)
        s += g_part[(size_t)(n * 16 + b) * G + k];
    g_ctx[n * G + k] = s * (1.0f / 4096.0f);
}

// ---- f-MLP + log_softmax ---------------------------------------------------
__global__ void k_fmlp(const float* __restrict__ fw1, const float* __restrict__ fb1,
                       const float* __restrict__ fw2, const float* __restrict__ fb2,
                       const float* __restrict__ fw3, const float* __restrict__ fb3,
                       float* __restrict__ out) {
    int n = blockIdx.x, tid = threadIdx.x;   // 512 threads
    __shared__ float x[G], y[G];
    __shared__ float sc[2];
    x[tid] = g_ctx[n * G + tid];
    __syncthreads();
    float s0 = fb1[tid], s1 = 0.f;
    #pragma unroll 8
    for (int c = 0; c < G; c += 2) {
        s0 = fmaf(x[c],     fw1[(size_t)c * G + tid], s0);
        s1 = fmaf(x[c + 1], fw1[(size_t)(c + 1) * G + tid], s1);
    }
    y[tid] = fmaxf(s0 + s1, 0.f);
    __syncthreads();
    s0 = fb2[tid]; s1 = 0.f;
    #pragma unroll 8
    for (int c = 0; c < G; c += 2) {
        s0 = fmaf(y[c],     fw2[(size_t)c * G + tid], s0);
        s1 = fmaf(y[c + 1], fw2[(size_t)(c + 1) * G + tid], s1);
    }
    x[tid] = fmaxf(s0 + s1, 0.f);
    __syncthreads();
    if (tid < 2) {
        float t = fb3[tid];
        for (int c = 0; c < G; ++c) t = fmaf(x[c], fw3[c * 2 + tid], t);
        sc[tid] = t;
    }
    __syncthreads();
    if (tid == 0) {
        float m = fmaxf(sc[0], sc[1]);
        float lse = m + logf(expf(sc[0] - m) + expf(sc[1] - m));
        out[n * 2 + 0] = sc[0] - lse;
        out[n * 2 + 1] = sc[1] - lse;
    }
}

// ---------------- host: tensormap building ----------------
typedef CUresult (*EncodeFn)(CUtensorMap*, CUtensorMapDataType, cuuint32_t, void*,
                             const cuuint64_t*, const cuuint64_t*, const cuuint32_t*,
                             const cuuint32_t*, CUtensorMapInterleave, CUtensorMapSwizzle,
                             CUtensorMapL2promotion, CUtensorMapFloatOOBfill);

static EncodeFn get_encoder() {
    void* fn = nullptr;
    cudaDriverEntryPointQueryResult st;
    cudaGetDriverEntryPoint("cuTensorMapEncodeTiled", &fn, cudaEnableDefault, &st);
    return (EncodeFn)fn;
}
static void build_map(EncodeFn enc, CUtensorMap* m, void* base,
                      unsigned long long rows, unsigned boxRows) {
    cuuint64_t dims[2]    = {(cuuint64_t)G, (cuuint64_t)rows};
    cuuint64_t strides[1] = {(cuuint64_t)G * 2};   // bf16 bytes
    cuuint32_t box[2]     = {(cuuint32_t)BK, (cuuint32_t)boxRows};
    cuuint32_t es[2]      = {1, 1};
    enc(m, CU_TENSOR_MAP_DATA_TYPE_BFLOAT16, 2, base, dims, strides, box, es,
        CU_TENSOR_MAP_INTERLEAVE_NONE, CU_TENSOR_MAP_SWIZZLE_64B,
        CU_TENSOR_MAP_L2_PROMOTION_L2_128B, CU_TENSOR_MAP_FLOAT_OOB_FILL_NONE);
}

// ----------------------------------------------------------------------------
extern "C" void kernel_launch(void* const* d_in, const int* in_sizes, int n_in,
                              void* d_out, int out_size) {
    const float* img  = (const float*)d_in[0];
    const float* ques = (const float*)d_in[1];
    const float* g_w1 = (const float*)d_in[2];
    const float* g_b1 = (const float*)d_in[3];
    const float* g_w2 = (const float*)d_in[4];
    const float* g_b2 = (const float*)d_in[5];
    const float* g_w3 = (const float*)d_in[6];
    const float* g_b3 = (const float*)d_in[7];
    const float* g_w4 = (const float*)d_in[8];
    const float* g_b4 = (const float*)d_in[9];
    const float* f_w1 = (const float*)d_in[10];
    const float* f_b1 = (const float*)d_in[11];
    const float* f_w2 = (const float*)d_in[12];
    const float* f_b2 = (const float*)d_in[13];
    const float* f_w3 = (const float*)d_in[14];
    const float* f_b3 = (const float*)d_in[15];
    float* out = (float*)d_out;

    cudaFuncSetAttribute(k_mma<0>, cudaFuncAttributeMaxDynamicSharedMemorySize, SMEM_SZ);
    cudaFuncSetAttribute(k_mma<1>, cudaFuncAttributeMaxDynamicSharedMemorySize, SMEM_SZ);
    cudaFuncSetAttribute(k_mma<2>, cudaFuncAttributeMaxDynamicSharedMemorySize, SMEM_SZ);

    unsigned short *w2h, *w2l, *w3h, *w3l, *w4h, *w4l, *h2h, *h2l, *h3h, *h3l;
    cudaGetSymbolAddress((void**)&w2h, g_w2h); cudaGetSymbolAddress((void**)&w2l, g_w2l);
    cudaGetSymbolAddress((void**)&w3h, g_w3h); cudaGetSymbolAddress((void**)&w3l, g_w3l);
    cudaGetSymbolAddress((void**)&w4h, g_w4h); cudaGetSymbolAddress((void**)&w4l, g_w4l);
    cudaGetSymbolAddress((void**)&h2h, g_h2h); cudaGetSymbolAddress((void**)&h2l, g_h2l);
    cudaGetSymbolAddress((void**)&h3h, g_h3h); cudaGetSymbolAddress((void**)&h3l, g_h3l);

    EncodeFn enc = get_encoder();
    CUtensorMap mW2h, mW2l, mW3h, mW3l, mW4h, mW4l, mA2h, mA2l, mA3h, mA3l;
    build_map(enc, &mW2h, w2h, G, BN);       build_map(enc, &mW2l, w2l, G, BN);
    build_map(enc, &mW3h, w3h, G, BN);       build_map(enc, &mW3l, w3l, G, BN);
    build_map(enc, &mW4h, w4h, G, BN);       build_map(enc, &mW4l, w4l, G, BN);
    build_map(enc, &mA2h, h2h, MROWS, BM);   build_map(enc, &mA2l, h2l, MROWS, BM);
    build_map(enc, &mA3h, h3h, MROWS, BM);   build_map(enc, &mA3l, h3l, MROWS, BM);

    k_wprep3<<<dim3(G, 3), G>>>(g_w2, g_w3, g_w4, w2h, w2l, w3h, w3l, w4h, w4l);
    k_ab<<<dim3(NB, 8), 512>>>(img, g_w1);
    k_cq<<<NB, 512>>>(ques, g_w1, g_b1);

    dim3 gg(MBLKS, G / BN);   // 1024 x 2
    k_mma<0><<<gg, THREADS, SMEM_SZ>>>(mW2h, mW2l, mW2h, mW2l, g_b2, h2h, h2l,
                                       nullptr, nullptr, w2h, w2l);
    k_mma<1><<<gg, THREADS, SMEM_SZ>>>(mA2h, mA2l, mW3h, mW3l, g_b3, h3h, h3l,
                                       h2h, h2l, w3h, w3l);
    k_mma<2><<<gg, THREADS, SMEM_SZ>>>(mA3h, mA3l, mW4h, mW4l, g_b4, nullptr, nullptr,
                                       h3h, h3l, w4h, w4l);

    k_reduce2<<<NB, 512>>>();
    k_fmlp<<<NB, 512>>>(f_w1, f_b1, f_w2, f_b2, f_w3, f_b3, out);
}